// round 1
// baseline (speedup 1.0000x reference)
#include <cuda_runtime.h>
#include <math.h>

#define SQ 2048
#define HD 1024
#define NHEAD 16
#define HNDIM 64
#define NLAYER 2

// ---------------- scratch (device globals; no allocations allowed) ----------
__device__ float g_h[SQ * HD];           // residual stream
__device__ float g_lnbuf[SQ * HD];       // layernorm output
__device__ float g_qkv[SQ * 3 * HD];     // qkv projection
__device__ float g_ctx[SQ * HD];         // attention context
__device__ float g_fc[SQ * 4 * HD];      // mlp hidden
__device__ float g_scores[NHEAD * SQ * SQ]; // attention scores/probs (268 MB)

// ---------------- helpers ----------------------------------------------------
__device__ __forceinline__ float gelu_f(float x) {
    return 0.5f * x * (1.0f + tanhf(0.7978845608028654f * x * (1.0f + 0.044715f * x * x)));
}

// ---------------- layernorm: one block per row -------------------------------
__global__ __launch_bounds__(256) void ln_kernel(const float* __restrict__ x,
                                                 const float* __restrict__ g,
                                                 const float* __restrict__ b,
                                                 float* __restrict__ out) {
    int row = blockIdx.x;
    const float* xr = x + (size_t)row * HD;
    float* outr = out + (size_t)row * HD;
    __shared__ float red[256];
    int t = threadIdx.x;

    float s = 0.0f;
    for (int i = t; i < HD; i += 256) s += xr[i];
    red[t] = s;
    __syncthreads();
    for (int o = 128; o > 0; o >>= 1) {
        if (t < o) red[t] += red[t + o];
        __syncthreads();
    }
    float mu = red[0] * (1.0f / HD);
    __syncthreads();

    float v = 0.0f;
    for (int i = t; i < HD; i += 256) {
        float d = xr[i] - mu;
        v += d * d;
    }
    red[t] = v;
    __syncthreads();
    for (int o = 128; o > 0; o >>= 1) {
        if (t < o) red[t] += red[t + o];
        __syncthreads();
    }
    float rstd = rsqrtf(red[0] * (1.0f / HD) + 1e-5f);

    for (int i = t; i < HD; i += 256)
        outr[i] = (xr[i] - mu) * rstd * g[i] + b[i];
}

// ---------------- generic fp32 GEMM ------------------------------------------
// C[z] = A[z] * B[z] (+bias) (+gelu) (+R)   per grid.z slice
// Tiles: BM=BN=64, BK=16. 256 threads, 4x4 per thread. All dims divisible.
__global__ __launch_bounds__(256) void gemm_kernel(
    const float* __restrict__ A, int lda, long long hsA,
    const float* __restrict__ B, int ldb, long long hsB,
    const float* __restrict__ bias,
    const float* __restrict__ R,
    float* __restrict__ C, int ldc, long long hsC,
    int K, int act, int causal) {
    __shared__ float As[16][64];
    __shared__ float Bs[16][64];

    A += (long long)blockIdx.z * hsA;
    B += (long long)blockIdx.z * hsB;
    C += (long long)blockIdx.z * hsC;
    if (R) R += (long long)blockIdx.z * hsC;

    int m0 = blockIdx.y * 64;
    int n0 = blockIdx.x * 64;
    int t = threadIdx.x;
    int ty = t >> 4, tx = t & 15;

    int Keff = causal ? (m0 + 64) : K;
    if (Keff > K) Keff = K;

    float acc[4][4] = {};

    for (int k0 = 0; k0 < Keff; k0 += 16) {
#pragma unroll
        for (int i = 0; i < 4; i++) {
            int idx = t + i * 256;
            int m = idx >> 4, k = idx & 15;
            As[k][m] = A[(long long)(m0 + m) * lda + k0 + k];
        }
#pragma unroll
        for (int i = 0; i < 4; i++) {
            int idx = t + i * 256;
            int k = idx >> 6, n = idx & 63;
            Bs[k][n] = B[(long long)(k0 + k) * ldb + n0 + n];
        }
        __syncthreads();
#pragma unroll
        for (int k = 0; k < 16; k++) {
            float a[4], b[4];
#pragma unroll
            for (int i = 0; i < 4; i++) a[i] = As[k][ty * 4 + i];
#pragma unroll
            for (int j = 0; j < 4; j++) b[j] = Bs[k][tx * 4 + j];
#pragma unroll
            for (int i = 0; i < 4; i++)
#pragma unroll
                for (int j = 0; j < 4; j++) acc[i][j] += a[i] * b[j];
        }
        __syncthreads();
    }

#pragma unroll
    for (int i = 0; i < 4; i++) {
#pragma unroll
        for (int j = 0; j < 4; j++) {
            int m = m0 + ty * 4 + i;
            int n = n0 + tx * 4 + j;
            float v = acc[i][j];
            if (bias) v += bias[n];
            if (act == 1) v = gelu_f(v);
            if (R) v += R[(long long)m * ldc + n];
            C[(long long)m * ldc + n] = v;
        }
    }
}

// ---------------- attention scores: Q*K^T per head, causal tiles only --------
__global__ __launch_bounds__(256) void scores_kernel(const float* __restrict__ qkv,
                                                     float* __restrict__ scores) {
    int kt = blockIdx.x, qt = blockIdx.y, h = blockIdx.z;
    if (kt > qt) return;  // never read by softmax/ctx

    __shared__ float Qs[64][65];
    __shared__ float Ks[64][65];

    const float* Q = qkv + h * HNDIM;            // row stride 3H
    const float* Kp = qkv + HD + h * HNDIM;

    int t = threadIdx.x;
#pragma unroll
    for (int i = 0; i < 16; i++) {
        int idx = t + i * 256;
        int r = idx >> 6, d = idx & 63;
        Qs[r][d] = Q[(long long)(qt * 64 + r) * (3 * HD) + d];
        Ks[r][d] = Kp[(long long)(kt * 64 + r) * (3 * HD) + d];
    }
    __syncthreads();

    int ty = t >> 4, tx = t & 15;
    float acc[4][4] = {};
#pragma unroll
    for (int k = 0; k < 64; k++) {
        float a[4], b[4];
#pragma unroll
        for (int i = 0; i < 4; i++) a[i] = Qs[ty * 4 + i][k];
#pragma unroll
        for (int j = 0; j < 4; j++) b[j] = Ks[tx * 4 + j][k];
#pragma unroll
        for (int i = 0; i < 4; i++)
#pragma unroll
            for (int j = 0; j < 4; j++) acc[i][j] += a[i] * b[j];
    }

    float* out = scores + ((long long)h * SQ + qt * 64) * SQ + kt * 64;
#pragma unroll
    for (int i = 0; i < 4; i++) {
#pragma unroll
        for (int j = 0; j < 4; j++) {
            int q = qt * 64 + ty * 4 + i;
            int kk = kt * 64 + tx * 4 + j;
            float v = (kk <= q) ? acc[i][j] * 0.125f : -10000.0f;
            out[(long long)(ty * 4 + i) * SQ + tx * 4 + j] = v;
        }
    }
}

// ---------------- softmax: one block per (q,h) row ---------------------------
__global__ __launch_bounds__(256) void softmax_kernel(float* __restrict__ scores) {
    int q = blockIdx.x, h = blockIdx.y;
    int len = ((q >> 6) << 6) + 64;  // full diagonal tile included
    float* row = scores + ((long long)h * SQ + q) * SQ;
    int t = threadIdx.x;
    __shared__ float red[256];

    float mx = -1e30f;
    for (int i = t; i < len; i += 256) mx = fmaxf(mx, row[i]);
    red[t] = mx;
    __syncthreads();
    for (int o = 128; o > 0; o >>= 1) {
        if (t < o) red[t] = fmaxf(red[t], red[t + o]);
        __syncthreads();
    }
    mx = red[0];
    __syncthreads();

    float s = 0.0f;
    for (int i = t; i < len; i += 256) {
        float e = expf(row[i] - mx);
        row[i] = e;
        s += e;
    }
    red[t] = s;
    __syncthreads();
    for (int o = 128; o > 0; o >>= 1) {
        if (t < o) red[t] += red[t + o];
        __syncthreads();
    }
    float inv = 1.0f / red[0];
    for (int i = t; i < len; i += 256) row[i] *= inv;
}

// ---------------- host orchestration -----------------------------------------
extern "C" void kernel_launch(void* const* d_in, const int* in_sizes, int n_in,
                              void* d_out, int out_size) {
    const float* x = (const float*)d_in[0];
    // d_in[1] = ltor_mask (causality applied analytically)
    const float* ln1_g = (const float*)d_in[2];
    const float* ln1_b = (const float*)d_in[3];
    const float* qkv_w = (const float*)d_in[4];
    const float* qkv_b = (const float*)d_in[5];
    const float* dense_w = (const float*)d_in[6];
    const float* dense_b = (const float*)d_in[7];
    const float* ln2_g = (const float*)d_in[8];
    const float* ln2_b = (const float*)d_in[9];
    const float* fc_w = (const float*)d_in[10];
    const float* fc_b = (const float*)d_in[11];
    const float* proj_w = (const float*)d_in[12];
    const float* proj_b = (const float*)d_in[13];
    const float* lnf_g = (const float*)d_in[14];
    const float* lnf_b = (const float*)d_in[15];

    float *h, *lnb, *qkv, *ctx, *fc, *sc;
    cudaGetSymbolAddress((void**)&h, g_h);
    cudaGetSymbolAddress((void**)&lnb, g_lnbuf);
    cudaGetSymbolAddress((void**)&qkv, g_qkv);
    cudaGetSymbolAddress((void**)&ctx, g_ctx);
    cudaGetSymbolAddress((void**)&fc, g_fc);
    cudaGetSymbolAddress((void**)&sc, g_scores);

    cudaMemcpyAsync(h, x, sizeof(float) * SQ * HD, cudaMemcpyDeviceToDevice, 0);

    for (int l = 0; l < NLAYER; l++) {
        // LN1
        ln_kernel<<<SQ, 256>>>(h, ln1_g + l * HD, ln1_b + l * HD, lnb);
        // QKV: [S,H] x [H,3H]
        gemm_kernel<<<dim3(3 * HD / 64, SQ / 64, 1), 256>>>(
            lnb, HD, 0, qkv_w + (long long)l * HD * 3 * HD, 3 * HD, 0,
            qkv_b + l * 3 * HD, nullptr, qkv, 3 * HD, 0, HD, 0, 0);
        // scores = Q K^T * scale, causal-masked
        scores_kernel<<<dim3(SQ / 64, SQ / 64, NHEAD), 256>>>(qkv, sc);
        // softmax rows
        softmax_kernel<<<dim3(SQ, NHEAD), 256>>>(sc);
        // ctx = P * V  (K truncated at diagonal tile)
        gemm_kernel<<<dim3(1, SQ / 64, NHEAD), 256>>>(
            sc, SQ, (long long)SQ * SQ, qkv + 2 * HD, 3 * HD, HNDIM,
            nullptr, nullptr, ctx, HD, HNDIM, SQ, 0, 1);
        // dense + residual: h = h + ctx*dw + db
        gemm_kernel<<<dim3(HD / 64, SQ / 64, 1), 256>>>(
            ctx, HD, 0, dense_w + (long long)l * HD * HD, HD, 0,
            dense_b + l * HD, h, h, HD, 0, HD, 0, 0);
        // LN2
        ln_kernel<<<SQ, 256>>>(h, ln2_g + l * HD, ln2_b + l * HD, lnb);
        // FC + gelu
        gemm_kernel<<<dim3(4 * HD / 64, SQ / 64, 1), 256>>>(
            lnb, HD, 0, fc_w + (long long)l * HD * 4 * HD, 4 * HD, 0,
            fc_b + l * 4 * HD, nullptr, fc, 4 * HD, 0, HD, 1, 0);
        // proj + residual: h = h + gelu(fc)*pw + pb
        gemm_kernel<<<dim3(HD / 64, SQ / 64, 1), 256>>>(
            fc, 4 * HD, 0, proj_w + (long long)l * 4 * HD * HD, HD, 0,
            proj_b + l * HD, h, h, HD, 0, 4 * HD, 0, 0);
    }
    // final layernorm -> output
    ln_kernel<<<SQ, 256>>>(h, lnf_g, lnf_b, (float*)d_out);
}

// round 2
// speedup vs baseline: 3.3763x; 3.3763x over previous
#include <cuda_runtime.h>
#include <math.h>
#include <stdint.h>

#define SQ 2048
#define HD 1024
#define NHEAD 16
#define HNDIM 64
#define NLAYER 2

#define BM 128
#define BN 64
#define BK 32

// ---------------- scratch (device globals; no allocations allowed) ----------
__device__ float g_h[SQ * HD];
__device__ float g_lnbuf[SQ * HD];
__device__ float g_qkv[SQ * 3 * HD];
__device__ float g_kT[NHEAD * HNDIM * SQ];          // K transposed per head [h][d][s]
__device__ float g_ctx[SQ * HD];
__device__ float g_fc[SQ * 4 * HD];
__device__ float g_scores[(size_t)NHEAD * SQ * SQ]; // 268 MB scores/probs

// ---------------- helpers ----------------------------------------------------
__device__ __forceinline__ float gelu_f(float x) {
    return 0.5f * x * (1.0f + tanhf(0.7978845608028654f * x * (1.0f + 0.044715f * x * x)));
}

__device__ __forceinline__ void mma8(float* d, const uint32_t* a, const uint32_t* b) {
    asm volatile(
        "mma.sync.aligned.m16n8k8.row.col.f32.tf32.tf32.f32 "
        "{%0,%1,%2,%3}, {%4,%5,%6,%7}, {%8,%9}, {%0,%1,%2,%3};\n"
        : "+f"(d[0]), "+f"(d[1]), "+f"(d[2]), "+f"(d[3])
        : "r"(a[0]), "r"(a[1]), "r"(a[2]), "r"(a[3]), "r"(b[0]), "r"(b[1]));
}

// ---------------- layernorm: one block per row -------------------------------
__global__ __launch_bounds__(256) void ln_kernel(const float* __restrict__ x,
                                                 const float* __restrict__ g,
                                                 const float* __restrict__ b,
                                                 float* __restrict__ out) {
    int row = blockIdx.x;
    const float* xr = x + (size_t)row * HD;
    float* outr = out + (size_t)row * HD;
    __shared__ float red[256];
    int t = threadIdx.x;

    float s = 0.0f;
    for (int i = t; i < HD; i += 256) s += xr[i];
    red[t] = s;
    __syncthreads();
    for (int o = 128; o > 0; o >>= 1) {
        if (t < o) red[t] += red[t + o];
        __syncthreads();
    }
    float mu = red[0] * (1.0f / HD);
    __syncthreads();

    float v = 0.0f;
    for (int i = t; i < HD; i += 256) {
        float d = xr[i] - mu;
        v += d * d;
    }
    red[t] = v;
    __syncthreads();
    for (int o = 128; o > 0; o >>= 1) {
        if (t < o) red[t] += red[t + o];
        __syncthreads();
    }
    float rstd = rsqrtf(red[0] * (1.0f / HD) + 1e-5f);

    for (int i = t; i < HD; i += 256)
        outr[i] = (xr[i] - mu) * rstd * g[i] + b[i];
}

// ---------------- K transpose: qkv K-part -> [h][d][s] -----------------------
__global__ void transpose_k(const float* __restrict__ qkv, float* __restrict__ kT) {
    __shared__ float tile[32][33];
    int h = blockIdx.z, s0 = blockIdx.x * 32, d0 = blockIdx.y * 32;
    int tx = threadIdx.x, ty = threadIdx.y;
#pragma unroll
    for (int i = 0; i < 32; i += 8)
        tile[ty + i][tx] = qkv[(long long)(s0 + ty + i) * (3 * HD) + HD + h * HNDIM + d0 + tx];
    __syncthreads();
#pragma unroll
    for (int i = 0; i < 32; i += 8)
        kT[(long long)h * HNDIM * SQ + (long long)(d0 + ty + i) * SQ + s0 + tx] = tile[tx][ty + i];
}

// ---------------- tensor-core tf32 GEMM --------------------------------------
// C[z] = A[z] * B[z] (+bias)(+gelu)(+R). BM=128,BN=64,BK=32, 256 thr (8 warps 4x2).
// scoresMode: skip blocks above causal diagonal, epilogue = *0.125 / -10000 mask.
// causal: truncate K loop at m0+BM (for P*V).
__global__ __launch_bounds__(256) void gemm_tc(
    const float* __restrict__ A, int lda, long long hsA,
    const float* __restrict__ B, int ldb, long long hsB,
    const float* __restrict__ bias,
    const float* __restrict__ R,
    float* __restrict__ C, int ldc, long long hsC,
    int K, int act, int causal, int scoresMode) {
    int m0 = blockIdx.y * BM;
    int n0 = blockIdx.x * BN;
    if (scoresMode && n0 >= m0 + BM) return;

    A += (long long)blockIdx.z * hsA;
    B += (long long)blockIdx.z * hsB;
    C += (long long)blockIdx.z * hsC;
    if (R) R += (long long)blockIdx.z * hsC;

    int Keff = causal ? (m0 + BM) : K;
    if (Keff > K) Keff = K;

    __shared__ float As[BM][BK + 4];   // [m][k], pad 4 -> conflict-free frag loads
    __shared__ float Bs[BK][BN + 8];   // [k][n], pad 8 -> conflict-free frag loads

    int t = threadIdx.x;
    int wid = t >> 5, lane = t & 31;
    int g = lane >> 2, tig = lane & 3;
    int wm = (wid & 3) * 32;   // warp tile 32x32
    int wn = (wid >> 2) * 32;

    float acc[2][4][4] = {};

    for (int k0 = 0; k0 < Keff; k0 += BK) {
#pragma unroll
        for (int i = 0; i < 4; i++) {   // A: 128x32 = 1024 float4
            int fid = t + i * 256;
            int r = fid >> 3, cf = fid & 7;
            float4 v = *(const float4*)(A + (long long)(m0 + r) * lda + k0 + cf * 4);
            *(float4*)&As[r][cf * 4] = v;
        }
#pragma unroll
        for (int i = 0; i < 2; i++) {   // B: 32x64 = 512 float4
            int fid = t + i * 256;
            int r = fid >> 4, cf = fid & 15;
            float4 v = *(const float4*)(B + (long long)(k0 + r) * ldb + n0 + cf * 4);
            *(float4*)&Bs[r][cf * 4] = v;
        }
        __syncthreads();

#pragma unroll
        for (int k8 = 0; k8 < BK; k8 += 8) {
            uint32_t a[2][4], b[4][2];
#pragma unroll
            for (int f = 0; f < 2; f++) {
                int mb = wm + f * 16 + g;
                a[f][0] = __float_as_uint(As[mb][k8 + tig]);
                a[f][1] = __float_as_uint(As[mb + 8][k8 + tig]);
                a[f][2] = __float_as_uint(As[mb][k8 + tig + 4]);
                a[f][3] = __float_as_uint(As[mb + 8][k8 + tig + 4]);
            }
#pragma unroll
            for (int j = 0; j < 4; j++) {
                int nb = wn + j * 8 + g;
                b[j][0] = __float_as_uint(Bs[k8 + tig][nb]);
                b[j][1] = __float_as_uint(Bs[k8 + tig + 4][nb]);
            }
#pragma unroll
            for (int f = 0; f < 2; f++)
#pragma unroll
                for (int j = 0; j < 4; j++) mma8(acc[f][j], a[f], b[j]);
        }
        __syncthreads();
    }

    // epilogue
#pragma unroll
    for (int f = 0; f < 2; f++) {
#pragma unroll
        for (int j = 0; j < 4; j++) {
            int n = n0 + wn + j * 8 + tig * 2;
#pragma unroll
            for (int half = 0; half < 2; half++) {
                int m = m0 + wm + f * 16 + g + half * 8;
                float v0 = acc[f][j][half * 2 + 0];
                float v1 = acc[f][j][half * 2 + 1];
                if (scoresMode) {
                    v0 = (n <= m) ? v0 * 0.125f : -10000.0f;
                    v1 = (n + 1 <= m) ? v1 * 0.125f : -10000.0f;
                } else {
                    if (bias) { v0 += bias[n]; v1 += bias[n + 1]; }
                    if (act) { v0 = gelu_f(v0); v1 = gelu_f(v1); }
                    if (R) {
                        float2 r2 = *(const float2*)(R + (long long)m * ldc + n);
                        v0 += r2.x; v1 += r2.y;
                    }
                }
                *(float2*)(C + (long long)m * ldc + n) = make_float2(v0, v1);
            }
        }
    }
}

// ---------------- softmax: single pass, values in registers ------------------
// len is 128-granular: padded masked entries hold -10000 -> exp underflows to 0,
// so the P*V GEMM can read full 128-row K tiles.
__global__ __launch_bounds__(256) void softmax2(float* __restrict__ sc) {
    int q = blockIdx.x, h = blockIdx.y;
    int len = ((q >> 7) << 7) + 128;
    float* row = sc + ((long long)h * SQ + q) * SQ;
    int t = threadIdx.x;
    __shared__ float red[8];

    float v[8];
    float mx = -1e30f;
#pragma unroll
    for (int j = 0; j < 8; j++) {
        int i = t + j * 256;
        if (i < len) { v[j] = row[i]; mx = fmaxf(mx, v[j]); }
    }
#pragma unroll
    for (int o = 16; o > 0; o >>= 1) mx = fmaxf(mx, __shfl_xor_sync(~0u, mx, o));
    if ((t & 31) == 0) red[t >> 5] = mx;
    __syncthreads();
    mx = red[0];
#pragma unroll
    for (int w = 1; w < 8; w++) mx = fmaxf(mx, red[w]);

    float s = 0.0f;
#pragma unroll
    for (int j = 0; j < 8; j++) {
        int i = t + j * 256;
        if (i < len) { float e = __expf(v[j] - mx); v[j] = e; s += e; }
    }
#pragma unroll
    for (int o = 16; o > 0; o >>= 1) s += __shfl_xor_sync(~0u, s, o);
    __syncthreads();
    if ((t & 31) == 0) red[t >> 5] = s;
    __syncthreads();
    s = 0.0f;
#pragma unroll
    for (int w = 0; w < 8; w++) s += red[w];
    float inv = 1.0f / s;

#pragma unroll
    for (int j = 0; j < 8; j++) {
        int i = t + j * 256;
        if (i < len) row[i] = v[j] * inv;
    }
}

// ---------------- host orchestration -----------------------------------------
extern "C" void kernel_launch(void* const* d_in, const int* in_sizes, int n_in,
                              void* d_out, int out_size) {
    const float* x = (const float*)d_in[0];
    const float* ln1_g = (const float*)d_in[2];
    const float* ln1_b = (const float*)d_in[3];
    const float* qkv_w = (const float*)d_in[4];
    const float* qkv_b = (const float*)d_in[5];
    const float* dense_w = (const float*)d_in[6];
    const float* dense_b = (const float*)d_in[7];
    const float* ln2_g = (const float*)d_in[8];
    const float* ln2_b = (const float*)d_in[9];
    const float* fc_w = (const float*)d_in[10];
    const float* fc_b = (const float*)d_in[11];
    const float* proj_w = (const float*)d_in[12];
    const float* proj_b = (const float*)d_in[13];
    const float* lnf_g = (const float*)d_in[14];
    const float* lnf_b = (const float*)d_in[15];

    float *h, *lnb, *qkv, *kT, *ctx, *fc, *sc;
    cudaGetSymbolAddress((void**)&h, g_h);
    cudaGetSymbolAddress((void**)&lnb, g_lnbuf);
    cudaGetSymbolAddress((void**)&qkv, g_qkv);
    cudaGetSymbolAddress((void**)&kT, g_kT);
    cudaGetSymbolAddress((void**)&ctx, g_ctx);
    cudaGetSymbolAddress((void**)&fc, g_fc);
    cudaGetSymbolAddress((void**)&sc, g_scores);

    cudaMemcpyAsync(h, x, sizeof(float) * SQ * HD, cudaMemcpyDeviceToDevice, 0);

    for (int l = 0; l < NLAYER; l++) {
        // LN1
        ln_kernel<<<SQ, 256>>>(h, ln1_g + l * HD, ln1_b + l * HD, lnb);
        // QKV: [S,H] x [H,3H]
        gemm_tc<<<dim3(3 * HD / BN, SQ / BM, 1), 256>>>(
            lnb, HD, 0, qkv_w + (long long)l * HD * 3 * HD, 3 * HD, 0,
            qkv_b + l * 3 * HD, nullptr, qkv, 3 * HD, 0, HD, 0, 0, 0);
        // K transpose per head -> [h][d][s]
        transpose_k<<<dim3(SQ / 32, HNDIM / 32, NHEAD), dim3(32, 8)>>>(qkv, kT);
        // scores = Q * K^T (scale + causal mask in epilogue, blocks above diag skipped)
        gemm_tc<<<dim3(SQ / BN, SQ / BM, NHEAD), 256>>>(
            qkv, 3 * HD, HNDIM, kT, SQ, (long long)HNDIM * SQ,
            nullptr, nullptr, sc, SQ, (long long)SQ * SQ, HNDIM, 0, 0, 1);
        // softmax rows (128-granular)
        softmax2<<<dim3(SQ, NHEAD), 256>>>(sc);
        // ctx = P * V (K truncated at diagonal block)
        gemm_tc<<<dim3(1, SQ / BM, NHEAD), 256>>>(
            sc, SQ, (long long)SQ * SQ, qkv + 2 * HD, 3 * HD, HNDIM,
            nullptr, nullptr, ctx, HD, HNDIM, SQ, 0, 1, 0);
        // dense + residual
        gemm_tc<<<dim3(HD / BN, SQ / BM, 1), 256>>>(
            ctx, HD, 0, dense_w + (long long)l * HD * HD, HD, 0,
            dense_b + l * HD, h, h, HD, 0, HD, 0, 0, 0);
        // LN2
        ln_kernel<<<SQ, 256>>>(h, ln2_g + l * HD, ln2_b + l * HD, lnb);
        // FC + gelu
        gemm_tc<<<dim3(4 * HD / BN, SQ / BM, 1), 256>>>(
            lnb, HD, 0, fc_w + (long long)l * HD * 4 * HD, 4 * HD, 0,
            fc_b + l * 4 * HD, nullptr, fc, 4 * HD, 0, HD, 1, 0, 0);
        // proj + residual
        gemm_tc<<<dim3(HD / BN, SQ / BM, 1), 256>>>(
            fc, 4 * HD, 0, proj_w + (long long)l * 4 * HD * HD, HD, 0,
            proj_b + l * HD, h, h, HD, 0, 4 * HD, 0, 0, 0);
    }
    // final layernorm -> output
    ln_kernel<<<SQ, 256>>>(h, lnf_g, lnf_b, (float*)d_out);
}

// round 3
// speedup vs baseline: 4.4017x; 1.3037x over previous
#include <cuda_runtime.h>
#include <math.h>
#include <stdint.h>

#define SQ 2048
#define HD 1024
#define NHEAD 16
#define HNDIM 64
#define NLAYER 2

#define BM 128
#define BK 32

// ---------------- scratch (device globals; no allocations allowed) ----------
__device__ float g_h[SQ * HD];
__device__ float g_lnbuf[SQ * HD];
__device__ float g_qkv[SQ * 3 * HD];
__device__ float g_kT[NHEAD * HNDIM * SQ];          // K transposed per head [h][d][s]
__device__ float g_ctx[SQ * HD];
__device__ float g_fc[SQ * 4 * HD];
__device__ float g_scores[(size_t)NHEAD * SQ * SQ]; // 268 MB scores/probs

// ---------------- helpers ----------------------------------------------------
__device__ __forceinline__ float gelu_f(float x) {
    return 0.5f * x * (1.0f + tanhf(0.7978845608028654f * x * (1.0f + 0.044715f * x * x)));
}

__device__ __forceinline__ void mma8(float* d, const uint32_t* a, const uint32_t* b) {
    asm volatile(
        "mma.sync.aligned.m16n8k8.row.col.f32.tf32.tf32.f32 "
        "{%0,%1,%2,%3}, {%4,%5,%6,%7}, {%8,%9}, {%0,%1,%2,%3};\n"
        : "+f"(d[0]), "+f"(d[1]), "+f"(d[2]), "+f"(d[3])
        : "r"(a[0]), "r"(a[1]), "r"(a[2]), "r"(a[3]), "r"(b[0]), "r"(b[1]));
}

__device__ __forceinline__ void cp16(uint32_t smem, const float* g) {
    asm volatile("cp.async.ca.shared.global [%0], [%1], 16;\n" :: "r"(smem), "l"(g));
}

// ---------------- layernorm ---------------------------------------------------
__global__ __launch_bounds__(256) void ln_kernel(const float* __restrict__ x,
                                                 const float* __restrict__ g,
                                                 const float* __restrict__ b,
                                                 float* __restrict__ out) {
    int row = blockIdx.x;
    const float* xr = x + (size_t)row * HD;
    float* outr = out + (size_t)row * HD;
    __shared__ float red[256];
    int t = threadIdx.x;

    float s = 0.0f;
    for (int i = t; i < HD; i += 256) s += xr[i];
    red[t] = s;
    __syncthreads();
    for (int o = 128; o > 0; o >>= 1) {
        if (t < o) red[t] += red[t + o];
        __syncthreads();
    }
    float mu = red[0] * (1.0f / HD);
    __syncthreads();

    float v = 0.0f;
    for (int i = t; i < HD; i += 256) {
        float d = xr[i] - mu;
        v += d * d;
    }
    red[t] = v;
    __syncthreads();
    for (int o = 128; o > 0; o >>= 1) {
        if (t < o) red[t] += red[t + o];
        __syncthreads();
    }
    float rstd = rsqrtf(red[0] * (1.0f / HD) + 1e-5f);

    for (int i = t; i < HD; i += 256)
        outr[i] = (xr[i] - mu) * rstd * g[i] + b[i];
}

// ---------------- K transpose -------------------------------------------------
__global__ void transpose_k(const float* __restrict__ qkv, float* __restrict__ kT) {
    __shared__ float tile[32][33];
    int h = blockIdx.z, s0 = blockIdx.x * 32, d0 = blockIdx.y * 32;
    int tx = threadIdx.x, ty = threadIdx.y;
#pragma unroll
    for (int i = 0; i < 32; i += 8)
        tile[ty + i][tx] = qkv[(long long)(s0 + ty + i) * (3 * HD) + HD + h * HNDIM + d0 + tx];
    __syncthreads();
#pragma unroll
    for (int i = 0; i < 32; i += 8)
        kT[(long long)h * HNDIM * SQ + (long long)(d0 + ty + i) * SQ + s0 + tx] = tile[tx][ty + i];
}

// ---------------- pipelined tensor-core tf32 GEMM -----------------------------
// Template: TBN = block N tile (128 or 64), WR = warps along M (2 or 4).
// 256 threads, 2-stage cp.async double buffer.
// scoresMode: skip blocks above causal diagonal, epilogue *0.125 / -10000 mask.
// causal: truncate K loop at m0+BM (for P*V).
template <int TBN, int WR>
__global__ __launch_bounds__(256, 2) void gemm_tc(
    const float* __restrict__ A, int lda, long long hsA,
    const float* __restrict__ B, int ldb, long long hsB,
    const float* __restrict__ bias,
    const float* __restrict__ R,
    float* __restrict__ C, int ldc, long long hsC,
    int K, int act, int causal, int scoresMode) {
    constexpr int WM = BM / WR;          // 64 / 32
    constexpr int WN = TBN / (8 / WR);   // 32
    constexpr int MF = WM / 16;          // 4 / 2
    constexpr int NF = WN / 8;           // 4
    constexpr int LDA = BK + 4;          // 36
    constexpr int LDB = TBN + 8;
    constexpr int STAGE = BM * LDA + BK * LDB;

    extern __shared__ float smem[];

    int m0 = blockIdx.y * BM;
    int n0 = blockIdx.x * TBN;
    if (scoresMode && n0 >= m0 + BM) return;

    A += (long long)blockIdx.z * hsA;
    B += (long long)blockIdx.z * hsB;
    C += (long long)blockIdx.z * hsC;
    if (R) R += (long long)blockIdx.z * hsC;

    int Keff = causal ? (m0 + BM) : K;
    if (Keff > K) Keff = K;
    int nTiles = Keff / BK;

    int t = threadIdx.x;
    int wid = t >> 5, lane = t & 31;
    int g = lane >> 2, tig = lane & 3;
    int wm = (wid % WR) * WM;
    int wn = (wid / WR) * WN;

    float acc[MF][NF][4] = {};

    // A-load indexing: 4 float4/thread; B: TBN/32 float4/thread
    int ar = t >> 3, ac = (t & 7) * 4;                 // A row / col(base) for i=0
    int br = t / (TBN / 4), bc = (t % (TBN / 4)) * 4;  // B row / col for i=0
    constexpr int A_RSTEP = 256 >> 3;                  // 32 rows per i
    constexpr int B_RSTEP = 256 / (TBN / 4);

#define LOAD_STAGE(ti, s)                                                             \
    {                                                                                 \
        float* As_ = smem + (s) * STAGE;                                              \
        float* Bs_ = As_ + BM * LDA;                                                  \
        int k0_ = (ti) * BK;                                                          \
        _Pragma("unroll") for (int i = 0; i < 4; i++) {                               \
            int r = ar + i * A_RSTEP;                                                 \
            cp16((uint32_t)__cvta_generic_to_shared(&As_[r * LDA + ac]),              \
                 A + (long long)(m0 + r) * lda + k0_ + ac);                           \
        }                                                                             \
        _Pragma("unroll") for (int i = 0; i < TBN / 32; i++) {                        \
            int r = br + i * B_RSTEP;                                                 \
            cp16((uint32_t)__cvta_generic_to_shared(&Bs_[r * LDB + bc]),              \
                 B + (long long)(k0_ + r) * ldb + n0 + bc);                           \
        }                                                                             \
        asm volatile("cp.async.commit_group;\n" ::: "memory");                        \
    }

    LOAD_STAGE(0, 0);

    for (int ti = 0; ti < nTiles; ti++) {
        asm volatile("cp.async.wait_group 0;\n" ::: "memory");
        __syncthreads();
        if (ti + 1 < nTiles) LOAD_STAGE(ti + 1, (ti + 1) & 1);

        const float* As = smem + (ti & 1) * STAGE;
        const float* Bs = As + BM * LDA;

#pragma unroll
        for (int k8 = 0; k8 < BK; k8 += 8) {
            uint32_t a[MF][4], b[NF][2];
#pragma unroll
            for (int f = 0; f < MF; f++) {
                int mb = wm + f * 16 + g;
                a[f][0] = __float_as_uint(As[mb * LDA + k8 + tig]);
                a[f][1] = __float_as_uint(As[(mb + 8) * LDA + k8 + tig]);
                a[f][2] = __float_as_uint(As[mb * LDA + k8 + tig + 4]);
                a[f][3] = __float_as_uint(As[(mb + 8) * LDA + k8 + tig + 4]);
            }
#pragma unroll
            for (int j = 0; j < NF; j++) {
                int nb = wn + j * 8 + g;
                b[j][0] = __float_as_uint(Bs[(k8 + tig) * LDB + nb]);
                b[j][1] = __float_as_uint(Bs[(k8 + tig + 4) * LDB + nb]);
            }
#pragma unroll
            for (int f = 0; f < MF; f++)
#pragma unroll
                for (int j = 0; j < NF; j++) mma8(acc[f][j], a[f], b[j]);
        }
    }

    // epilogue
#pragma unroll
    for (int f = 0; f < MF; f++) {
#pragma unroll
        for (int j = 0; j < NF; j++) {
            int n = n0 + wn + j * 8 + tig * 2;
#pragma unroll
            for (int half = 0; half < 2; half++) {
                int m = m0 + wm + f * 16 + g + half * 8;
                float v0 = acc[f][j][half * 2 + 0];
                float v1 = acc[f][j][half * 2 + 1];
                if (scoresMode) {
                    v0 = (n <= m) ? v0 * 0.125f : -10000.0f;
                    v1 = (n + 1 <= m) ? v1 * 0.125f : -10000.0f;
                } else {
                    if (bias) { v0 += bias[n]; v1 += bias[n + 1]; }
                    if (act) { v0 = gelu_f(v0); v1 = gelu_f(v1); }
                    if (R) {
                        float2 r2 = *(const float2*)(R + (long long)m * ldc + n);
                        v0 += r2.x; v1 += r2.y;
                    }
                }
                *(float2*)(C + (long long)m * ldc + n) = make_float2(v0, v1);
            }
        }
    }
#undef LOAD_STAGE
}

// ---------------- softmax: single pass, values in registers -------------------
__global__ __launch_bounds__(256) void softmax2(float* __restrict__ sc) {
    int q = blockIdx.x, h = blockIdx.y;
    int len = ((q >> 7) << 7) + 128;  // 128-granular: padded entries -> exp == 0
    float* row = sc + ((long long)h * SQ + q) * SQ;
    int t = threadIdx.x;
    __shared__ float red[8];

    float v[8];
    float mx = -1e30f;
#pragma unroll
    for (int j = 0; j < 8; j++) {
        int i = t + j * 256;
        if (i < len) { v[j] = row[i]; mx = fmaxf(mx, v[j]); }
    }
#pragma unroll
    for (int o = 16; o > 0; o >>= 1) mx = fmaxf(mx, __shfl_xor_sync(~0u, mx, o));
    if ((t & 31) == 0) red[t >> 5] = mx;
    __syncthreads();
    mx = red[0];
#pragma unroll
    for (int w = 1; w < 8; w++) mx = fmaxf(mx, red[w]);

    float s = 0.0f;
#pragma unroll
    for (int j = 0; j < 8; j++) {
        int i = t + j * 256;
        if (i < len) { float e = __expf(v[j] - mx); v[j] = e; s += e; }
    }
#pragma unroll
    for (int o = 16; o > 0; o >>= 1) s += __shfl_xor_sync(~0u, s, o);
    __syncthreads();
    if ((t & 31) == 0) red[t >> 5] = s;
    __syncthreads();
    s = 0.0f;
#pragma unroll
    for (int w = 0; w < 8; w++) s += red[w];
    float inv = 1.0f / s;

#pragma unroll
    for (int j = 0; j < 8; j++) {
        int i = t + j * 256;
        if (i < len) row[i] = v[j] * inv;
    }
}

// ---------------- host orchestration ------------------------------------------
extern "C" void kernel_launch(void* const* d_in, const int* in_sizes, int n_in,
                              void* d_out, int out_size) {
    const float* x = (const float*)d_in[0];
    const float* ln1_g = (const float*)d_in[2];
    const float* ln1_b = (const float*)d_in[3];
    const float* qkv_w = (const float*)d_in[4];
    const float* qkv_b = (const float*)d_in[5];
    const float* dense_w = (const float*)d_in[6];
    const float* dense_b = (const float*)d_in[7];
    const float* ln2_g = (const float*)d_in[8];
    const float* ln2_b = (const float*)d_in[9];
    const float* fc_w = (const float*)d_in[10];
    const float* fc_b = (const float*)d_in[11];
    const float* proj_w = (const float*)d_in[12];
    const float* proj_b = (const float*)d_in[13];
    const float* lnf_g = (const float*)d_in[14];
    const float* lnf_b = (const float*)d_in[15];

    float *h, *lnb, *qkv, *kT, *ctx, *fc, *sc;
    cudaGetSymbolAddress((void**)&h, g_h);
    cudaGetSymbolAddress((void**)&lnb, g_lnbuf);
    cudaGetSymbolAddress((void**)&qkv, g_qkv);
    cudaGetSymbolAddress((void**)&kT, g_kT);
    cudaGetSymbolAddress((void**)&ctx, g_ctx);
    cudaGetSymbolAddress((void**)&fc, g_fc);
    cudaGetSymbolAddress((void**)&sc, g_scores);

    const int SM128 = 2 * (BM * (BK + 4) + BK * (128 + 8)) * 4;  // 71680 B
    const int SM64 = 2 * (BM * (BK + 4) + BK * (64 + 8)) * 4;    // 55296 B
    cudaFuncSetAttribute(gemm_tc<128, 2>, cudaFuncAttributeMaxDynamicSharedMemorySize, SM128);
    cudaFuncSetAttribute(gemm_tc<64, 4>, cudaFuncAttributeMaxDynamicSharedMemorySize, SM64);

    cudaMemcpyAsync(h, x, sizeof(float) * SQ * HD, cudaMemcpyDeviceToDevice, 0);

    for (int l = 0; l < NLAYER; l++) {
        // LN1
        ln_kernel<<<SQ, 256>>>(h, ln1_g + l * HD, ln1_b + l * HD, lnb);
        // QKV: [S,H] x [H,3H]
        gemm_tc<128, 2><<<dim3(3 * HD / 128, SQ / BM, 1), 256, SM128>>>(
            lnb, HD, 0, qkv_w + (long long)l * HD * 3 * HD, 3 * HD, 0,
            qkv_b + l * 3 * HD, nullptr, qkv, 3 * HD, 0, HD, 0, 0, 0);
        // K transpose per head -> [h][d][s]
        transpose_k<<<dim3(SQ / 32, HNDIM / 32, NHEAD), dim3(32, 8)>>>(qkv, kT);
        // scores = Q * K^T (scale + causal mask in epilogue, upper blocks skipped)
        gemm_tc<128, 2><<<dim3(SQ / 128, SQ / BM, NHEAD), 256, SM128>>>(
            qkv, 3 * HD, HNDIM, kT, SQ, (long long)HNDIM * SQ,
            nullptr, nullptr, sc, SQ, (long long)SQ * SQ, HNDIM, 0, 0, 1);
        // softmax rows (128-granular)
        softmax2<<<dim3(SQ, NHEAD), 256>>>(sc);
        // ctx = P * V (K truncated at diagonal block)
        gemm_tc<64, 4><<<dim3(1, SQ / BM, NHEAD), 256, SM64>>>(
            sc, SQ, (long long)SQ * SQ, qkv + 2 * HD, 3 * HD, HNDIM,
            nullptr, nullptr, ctx, HD, HNDIM, SQ, 0, 1, 0);
        // dense + residual
        gemm_tc<128, 2><<<dim3(HD / 128, SQ / BM, 1), 256, SM128>>>(
            ctx, HD, 0, dense_w + (long long)l * HD * HD, HD, 0,
            dense_b + l * HD, h, h, HD, 0, HD, 0, 0, 0);
        // LN2
        ln_kernel<<<SQ, 256>>>(h, ln2_g + l * HD, ln2_b + l * HD, lnb);
        // FC + gelu
        gemm_tc<128, 2><<<dim3(4 * HD / 128, SQ / BM, 1), 256, SM128>>>(
            lnb, HD, 0, fc_w + (long long)l * HD * 4 * HD, 4 * HD, 0,
            fc_b + l * 4 * HD, nullptr, fc, 4 * HD, 0, HD, 1, 0, 0);
        // proj + residual
        gemm_tc<128, 2><<<dim3(HD / 128, SQ / BM, 1), 256, SM128>>>(
            fc, 4 * HD, 0, proj_w + (long long)l * 4 * HD * HD, HD, 0,
            proj_b + l * HD, h, h, HD, 0, 4 * HD, 0, 0, 0);
    }
    // final layernorm -> output
    ln_kernel<<<SQ, 256>>>(h, lnf_g, lnf_b, (float*)d_out);
}

// round 5
// speedup vs baseline: 6.1319x; 1.3931x over previous
#include <cuda_runtime.h>
#include <cuda_fp16.h>
#include <math.h>
#include <stdint.h>

#define SQ 2048
#define HD 1024
#define NHEAD 16
#define HNDIM 64
#define NLAYER 2

#define BM 128
#define BK 32      // halves per K-tile
#define LDK 40     // padded row length (halves) -> 80B stride, LDSM conflict-free
#define NST 3      // pipeline stages

// ---------------- scratch (device globals; no allocations allowed) ----------
__device__ float g_h[SQ * HD];                       // fp32 residual stream
__device__ __half g_lnb16[SQ * HD];                  // LN out (GEMM A operand)
__device__ __half g_qkv16[SQ * 3 * HD];              // qkv (fp16)
__device__ __half g_vT16[NHEAD * HNDIM * SQ];        // V transposed [h][d][s]
__device__ __half g_ctx16[SQ * HD];
__device__ __half g_fc16[SQ * 4 * HD];
__device__ float g_scores[(size_t)NHEAD * SQ * SQ];  // fp32 logits (softmax)
__device__ __half g_probs16[(size_t)NHEAD * SQ * SQ];
// fp16 transposed weights [N,K]
__device__ __half g_qkvwT[NLAYER * 3 * HD * HD];
__device__ __half g_densewT[NLAYER * HD * HD];
__device__ __half g_fcwT[NLAYER * 4 * HD * HD];
__device__ __half g_projwT[NLAYER * 4 * HD * HD];

// ---------------- helpers ----------------------------------------------------
__device__ __forceinline__ float gelu_f(float x) {
    return 0.5f * x * (1.0f + tanhf(0.7978845608028654f * x * (1.0f + 0.044715f * x * x)));
}

__device__ __forceinline__ void cp16h(uint32_t smem, const __half* g) {
    asm volatile("cp.async.ca.shared.global [%0], [%1], 16;\n" :: "r"(smem), "l"(g));
}

__device__ __forceinline__ void ldsm4(uint32_t* r, uint32_t addr) {
    asm volatile("ldmatrix.sync.aligned.m8n8.x4.shared.b16 {%0,%1,%2,%3}, [%4];"
                 : "=r"(r[0]), "=r"(r[1]), "=r"(r[2]), "=r"(r[3]) : "r"(addr));
}

__device__ __forceinline__ void mma16(float* d, const uint32_t* a, const uint32_t* b) {
    asm volatile(
        "mma.sync.aligned.m16n8k16.row.col.f32.f16.f16.f32 "
        "{%0,%1,%2,%3}, {%4,%5,%6,%7}, {%8,%9}, {%0,%1,%2,%3};\n"
        : "+f"(d[0]), "+f"(d[1]), "+f"(d[2]), "+f"(d[3])
        : "r"(a[0]), "r"(a[1]), "r"(a[2]), "r"(a[3]), "r"(b[0]), "r"(b[1]));
}

// ---------------- layernorm (templated output type) ---------------------------
template <typename OUT>
__global__ __launch_bounds__(256) void ln_kernel(const float* __restrict__ x,
                                                 const float* __restrict__ g,
                                                 const float* __restrict__ b,
                                                 OUT* __restrict__ out) {
    int row = blockIdx.x;
    const float* xr = x + (size_t)row * HD;
    OUT* outr = out + (size_t)row * HD;
    __shared__ float red[256];
    int t = threadIdx.x;

    float s = 0.0f;
    for (int i = t; i < HD; i += 256) s += xr[i];
    red[t] = s;
    __syncthreads();
    for (int o = 128; o > 0; o >>= 1) {
        if (t < o) red[t] += red[t + o];
        __syncthreads();
    }
    float mu = red[0] * (1.0f / HD);
    __syncthreads();

    float v = 0.0f;
    for (int i = t; i < HD; i += 256) {
        float d = xr[i] - mu;
        v += d * d;
    }
    red[t] = v;
    __syncthreads();
    for (int o = 128; o > 0; o >>= 1) {
        if (t < o) red[t] += red[t + o];
        __syncthreads();
    }
    float rstd = rsqrtf(red[0] * (1.0f / HD) + 1e-5f);

    for (int i = t; i < HD; i += 256)
        outr[i] = (OUT)((xr[i] - mu) * rstd * g[i] + b[i]);
}

// ---------------- weight transpose+convert: W[K,N] fp32 -> Wt[N,K] fp16 ------
__global__ void transpose_w_h(const float* __restrict__ W, __half* __restrict__ Wt,
                              int Kd, int Nd) {
    __shared__ float tile[32][33];
    long long zo = (long long)blockIdx.z * Kd * Nd;
    int n0 = blockIdx.x * 32, k0 = blockIdx.y * 32;
    int tx = threadIdx.x, ty = threadIdx.y;
#pragma unroll
    for (int i = 0; i < 32; i += 8)
        tile[ty + i][tx] = W[zo + (long long)(k0 + ty + i) * Nd + n0 + tx];
    __syncthreads();
#pragma unroll
    for (int i = 0; i < 32; i += 8)
        Wt[zo + (long long)(n0 + ty + i) * Kd + k0 + tx] = __float2half(tile[tx][ty + i]);
}

// ---------------- V transpose: qkv16 V-part -> [h][d][s] fp16 -----------------
__global__ void transpose_v16(const __half* __restrict__ qkv, __half* __restrict__ vT) {
    __shared__ __half tile[32][34];
    int h = blockIdx.z, s0 = blockIdx.x * 32, d0 = blockIdx.y * 32;
    int tx = threadIdx.x, ty = threadIdx.y;
#pragma unroll
    for (int i = 0; i < 32; i += 8)
        tile[ty + i][tx] = qkv[(long long)(s0 + ty + i) * (3 * HD) + 2 * HD + h * HNDIM + d0 + tx];
    __syncthreads();
#pragma unroll
    for (int i = 0; i < 32; i += 8)
        vT[(long long)h * HNDIM * SQ + (long long)(d0 + ty + i) * SQ + s0 + tx] = tile[tx][ty + i];
}

// ---------------- fp16 tensor-core GEMM engine --------------------------------
// C[z] = A[z] (row-major [M,K]) x B[z]^T (B stored [N,K], k-major).
// TBN: block N tile (128 or 64). OUTH: 1 -> __half output, 0 -> float output.
// 256 threads, 8 warps (4 along M x 2 along N), warp tile 32 x (TBN/2).
// 3-stage cp.async ring; ldmatrix fragment loads; mma.m16n8k16.f16.
template <int TBN, int OUTH>
__global__ __launch_bounds__(256, 2) void hgemm(
    const __half* __restrict__ A, int lda, long long hsA,
    const __half* __restrict__ B, int ldb, long long hsB,
    const float* __restrict__ bias,
    const float* __restrict__ R,
    void* __restrict__ Cv, int ldc, long long hsC,
    int K, int act, int causal, int scoresMode) {
    constexpr int NF = TBN / 16;
    constexpr int ASZ = BM * LDK * 2;
    constexpr int BSZ = TBN * LDK * 2;
    constexpr int STB = ASZ + BSZ;
    constexpr int B_CP = (TBN * BK / 8) / 256;

    extern __shared__ __align__(16) char smem[];
    uint32_t sb;
    asm("{ .reg .u64 tmp; cvta.to.shared.u64 tmp, %1; cvt.u32.u64 %0, tmp; }"
        : "=r"(sb) : "l"(smem));

    int m0 = blockIdx.y * BM;
    int n0 = blockIdx.x * TBN;
    if (scoresMode && n0 >= m0 + BM) return;

    A += (long long)blockIdx.z * hsA;
    B += (long long)blockIdx.z * hsB;

    int Keff = causal ? (m0 + BM) : K;
    if (Keff > K) Keff = K;
    int T = Keff / BK;

    int t = threadIdx.x;
    int wid = t >> 5, lane = t & 31;
    int g = lane >> 2, tig = lane & 3;
    int wm = (wid & 3) * 32;
    int wn = (wid >> 2) * (TBN / 2);

    const __half* Ag0 = A + (long long)m0 * lda;
    const __half* Bg0 = B + (long long)n0 * ldb;

    float acc[2][NF][4] = {};

#define LOADST(ti)                                                                \
    {                                                                             \
        uint32_t as_ = sb + ((ti) % NST) * STB;                                   \
        uint32_t bs_ = as_ + ASZ;                                                 \
        const __half* Ag_ = Ag0 + (long long)(ti) * BK;                           \
        const __half* Bg_ = Bg0 + (long long)(ti) * BK;                           \
        _Pragma("unroll") for (int i = 0; i < 2; i++) {                           \
            int id = t + i * 256;                                                 \
            int r = id >> 2, c = (id & 3) * 8;                                    \
            cp16h(as_ + (r * LDK + c) * 2, Ag_ + (long long)r * lda + c);         \
        }                                                                         \
        _Pragma("unroll") for (int i = 0; i < B_CP; i++) {                        \
            int id = t + i * 256;                                                 \
            int r = id >> 2, c = (id & 3) * 8;                                    \
            cp16h(bs_ + (r * LDK + c) * 2, Bg_ + (long long)r * ldb + c);         \
        }                                                                         \
        asm volatile("cp.async.commit_group;\n" ::: "memory");                    \
    }

    int loaded = 0;
    for (; loaded < 2 && loaded < T; loaded++) LOADST(loaded);

    int lrow = lane & 15, lcol = (lane >> 4) << 3;

    for (int ti = 0; ti < T; ti++) {
        if (loaded - ti >= 2) asm volatile("cp.async.wait_group 1;\n" ::: "memory");
        else asm volatile("cp.async.wait_group 0;\n" ::: "memory");
        __syncthreads();
        if (loaded < T) { LOADST(loaded); loaded++; }

        uint32_t as = sb + (ti % NST) * STB;
        uint32_t bs = as + ASZ;

#pragma unroll
        for (int kk = 0; kk < 2; kk++) {
            int k16 = kk * 16;
            uint32_t a[2][4];
#pragma unroll
            for (int f = 0; f < 2; f++)
                ldsm4(a[f], as + ((wm + f * 16 + lrow) * LDK + k16 + lcol) * 2);
            uint32_t bf[NF][2];
#pragma unroll
            for (int jp = 0; jp < NF / 2; jp++) {
                uint32_t r4[4];
                ldsm4(r4, bs + ((wn + jp * 16 + lrow) * LDK + k16 + lcol) * 2);
                bf[2 * jp][0] = r4[0]; bf[2 * jp][1] = r4[2];
                bf[2 * jp + 1][0] = r4[1]; bf[2 * jp + 1][1] = r4[3];
            }
#pragma unroll
            for (int f = 0; f < 2; f++)
#pragma unroll
                for (int j = 0; j < NF; j++) mma16(acc[f][j], a[f], bf[j]);
        }
    }
#undef LOADST

    long long co = (long long)blockIdx.z * hsC;
#pragma unroll
    for (int f = 0; f < 2; f++) {
#pragma unroll
        for (int j = 0; j < NF; j++) {
            int n = n0 + wn + j * 8 + tig * 2;
#pragma unroll
            for (int half_ = 0; half_ < 2; half_++) {
                int m = m0 + wm + f * 16 + g + half_ * 8;
                float v0 = acc[f][j][half_ * 2 + 0];
                float v1 = acc[f][j][half_ * 2 + 1];
                if (scoresMode) {
                    v0 = (n <= m) ? v0 * 0.125f : -10000.0f;
                    v1 = (n + 1 <= m) ? v1 * 0.125f : -10000.0f;
                } else {
                    if (bias) {
                        float2 bb = *(const float2*)(bias + n);
                        v0 += bb.x; v1 += bb.y;
                    }
                    if (act) { v0 = gelu_f(v0); v1 = gelu_f(v1); }
                    if (R) {
                        float2 rr = *(const float2*)(R + co + (long long)m * ldc + n);
                        v0 += rr.x; v1 += rr.y;
                    }
                }
                if (OUTH) {
                    __half2* out = (__half2*)((__half*)Cv + co + (long long)m * ldc + n);
                    *out = __floats2half2_rn(v0, v1);
                } else {
                    float2* out = (float2*)((float*)Cv + co + (long long)m * ldc + n);
                    *out = make_float2(v0, v1);
                }
            }
        }
    }
}

// ---------------- softmax: fp32 logits in, fp16 probs out ---------------------
__global__ __launch_bounds__(256) void softmax_h(const float* __restrict__ sc,
                                                 __half* __restrict__ pr) {
    int q = blockIdx.x, h = blockIdx.y;
    int len = ((q >> 7) << 7) + 128;
    const float* row = sc + ((long long)h * SQ + q) * SQ;
    __half* orow = pr + ((long long)h * SQ + q) * SQ;
    int t = threadIdx.x;
    __shared__ float red[8];

    float v[8];
    float mx = -1e30f;
#pragma unroll
    for (int j = 0; j < 8; j++) {
        int i = t + j * 256;
        if (i < len) { v[j] = row[i]; mx = fmaxf(mx, v[j]); }
    }
#pragma unroll
    for (int o = 16; o > 0; o >>= 1) mx = fmaxf(mx, __shfl_xor_sync(~0u, mx, o));
    if ((t & 31) == 0) red[t >> 5] = mx;
    __syncthreads();
    mx = red[0];
#pragma unroll
    for (int w = 1; w < 8; w++) mx = fmaxf(mx, red[w]);

    float s = 0.0f;
#pragma unroll
    for (int j = 0; j < 8; j++) {
        int i = t + j * 256;
        if (i < len) { float e = __expf(v[j] - mx); v[j] = e; s += e; }
    }
#pragma unroll
    for (int o = 16; o > 0; o >>= 1) s += __shfl_xor_sync(~0u, s, o);
    __syncthreads();
    if ((t & 31) == 0) red[t >> 5] = s;
    __syncthreads();
    s = 0.0f;
#pragma unroll
    for (int w = 0; w < 8; w++) s += red[w];
    float inv = 1.0f / s;

#pragma unroll
    for (int j = 0; j < 8; j++) {
        int i = t + j * 256;
        if (i < len) orow[i] = __float2half(v[j] * inv);
    }
}

// ---------------- host orchestration ------------------------------------------
extern "C" void kernel_launch(void* const* d_in, const int* in_sizes, int n_in,
                              void* d_out, int out_size) {
    const float* x = (const float*)d_in[0];
    const float* ln1_g = (const float*)d_in[2];
    const float* ln1_b = (const float*)d_in[3];
    const float* qkv_w = (const float*)d_in[4];
    const float* qkv_b = (const float*)d_in[5];
    const float* dense_w = (const float*)d_in[6];
    const float* dense_b = (const float*)d_in[7];
    const float* ln2_g = (const float*)d_in[8];
    const float* ln2_b = (const float*)d_in[9];
    const float* fc_w = (const float*)d_in[10];
    const float* fc_b = (const float*)d_in[11];
    const float* proj_w = (const float*)d_in[12];
    const float* proj_b = (const float*)d_in[13];
    const float* lnf_g = (const float*)d_in[14];
    const float* lnf_b = (const float*)d_in[15];

    float *h, *sc;
    __half *lnb16, *qkv16, *vT16, *ctx16, *fc16, *pr16;
    __half *qkvwT, *densewT, *fcwT, *projwT;
    cudaGetSymbolAddress((void**)&h, g_h);
    cudaGetSymbolAddress((void**)&sc, g_scores);
    cudaGetSymbolAddress((void**)&lnb16, g_lnb16);
    cudaGetSymbolAddress((void**)&qkv16, g_qkv16);
    cudaGetSymbolAddress((void**)&vT16, g_vT16);
    cudaGetSymbolAddress((void**)&ctx16, g_ctx16);
    cudaGetSymbolAddress((void**)&fc16, g_fc16);
    cudaGetSymbolAddress((void**)&pr16, g_probs16);
    cudaGetSymbolAddress((void**)&qkvwT, g_qkvwT);
    cudaGetSymbolAddress((void**)&densewT, g_densewT);
    cudaGetSymbolAddress((void**)&fcwT, g_fcwT);
    cudaGetSymbolAddress((void**)&projwT, g_projwT);

    const int SMH128 = NST * (BM * LDK * 2 + 128 * LDK * 2);  // 61440
    const int SMH64 = NST * (BM * LDK * 2 + 64 * LDK * 2);    // 46080
    cudaFuncSetAttribute(hgemm<128, 0>, cudaFuncAttributeMaxDynamicSharedMemorySize, SMH128);
    cudaFuncSetAttribute(hgemm<128, 1>, cudaFuncAttributeMaxDynamicSharedMemorySize, SMH128);
    cudaFuncSetAttribute(hgemm<64, 1>, cudaFuncAttributeMaxDynamicSharedMemorySize, SMH64);

    cudaMemcpyAsync(h, x, sizeof(float) * SQ * HD, cudaMemcpyDeviceToDevice, 0);

    transpose_w_h<<<dim3(3 * HD / 32, HD / 32, NLAYER), dim3(32, 8)>>>(qkv_w, qkvwT, HD, 3 * HD);
    transpose_w_h<<<dim3(HD / 32, HD / 32, NLAYER), dim3(32, 8)>>>(dense_w, densewT, HD, HD);
    transpose_w_h<<<dim3(4 * HD / 32, HD / 32, NLAYER), dim3(32, 8)>>>(fc_w, fcwT, HD, 4 * HD);
    transpose_w_h<<<dim3(HD / 32, 4 * HD / 32, NLAYER), dim3(32, 8)>>>(proj_w, projwT, 4 * HD, HD);

    for (int l = 0; l < NLAYER; l++) {
        // LN1 -> fp16
        ln_kernel<__half><<<SQ, 256>>>(h, ln1_g + l * HD, ln1_b + l * HD, lnb16);
        // QKV
        hgemm<128, 1><<<dim3(3 * HD / 128, SQ / BM), 256, SMH128>>>(
            lnb16, HD, 0, qkvwT + (long long)l * 3 * HD * HD, HD, 0,
            qkv_b + l * 3 * HD, nullptr, qkv16, 3 * HD, 0, HD, 0, 0, 0);
        // scores = Q K^T (no transpose needed: K rows are k-major B)
        hgemm<128, 0><<<dim3(SQ / 128, SQ / BM, NHEAD), 256, SMH128>>>(
            qkv16, 3 * HD, HNDIM, qkv16 + HD, 3 * HD, HNDIM,
            nullptr, nullptr, sc, SQ, (long long)SQ * SQ, HNDIM, 0, 0, 1);
        // softmax -> fp16 probs
        softmax_h<<<dim3(SQ, NHEAD), 256>>>(sc, pr16);
        // V transpose per head (PV B operand)
        transpose_v16<<<dim3(SQ / 32, HNDIM / 32, NHEAD), dim3(32, 8)>>>(qkv16, vT16);
        // ctx = P V
        hgemm<64, 1><<<dim3(1, SQ / BM, NHEAD), 256, SMH64>>>(
            pr16, SQ, (long long)SQ * SQ, vT16, SQ, (long long)HNDIM * SQ,
            nullptr, nullptr, ctx16, HD, HNDIM, SQ, 0, 1, 0);
        // dense + residual -> fp32 h
        hgemm<128, 0><<<dim3(HD / 128, SQ / BM), 256, SMH128>>>(
            ctx16, HD, 0, densewT + (long long)l * HD * HD, HD, 0,
            dense_b + l * HD, h, h, HD, 0, HD, 0, 0, 0);
        // LN2 -> fp16
        ln_kernel<__half><<<SQ, 256>>>(h, ln2_g + l * HD, ln2_b + l * HD, lnb16);
        // FC + gelu -> fp16
        hgemm<128, 1><<<dim3(4 * HD / 128, SQ / BM), 256, SMH128>>>(
            lnb16, HD, 0, fcwT + (long long)l * 4 * HD * HD, HD, 0,
            fc_b + l * 4 * HD, nullptr, fc16, 4 * HD, 0, HD, 1, 0, 0);
        // proj + residual -> fp32 h
        hgemm<128, 0><<<dim3(HD / 128, SQ / BM), 256, SMH128>>>(
            fc16, 4 * HD, 0, projwT + (long long)l * 4 * HD * HD, 4 * HD, 0,
            proj_b + l * HD, h, h, HD, 0, 4 * HD, 0, 0, 0);
    }
    ln_kernel<float><<<SQ, 256>>>(h, lnf_g, lnf_b, (float*)d_out);
}

// round 7
// speedup vs baseline: 7.9662x; 1.2992x over previous
#include <cuda_runtime.h>
#include <cuda_fp16.h>
#include <math.h>
#include <stdint.h>

#define SQ 2048
#define HD 1024
#define NHEAD 16
#define HNDIM 64
#define NLAYER 2

#define BM 128
#define BK 32      // halves per K-tile (GEMM)
#define LDK 40     // padded GEMM smem row (halves)
#define NST 3      // GEMM pipeline stages

// flash attention tiles
#define FLDQ 72                       // padded row length (halves) for Q/K/V tiles
#define FKVB (128 * FLDQ * 2)         // bytes per 128x64 tile = 18432
#define FSTG (2 * FKVB)               // K+V per stage
#define FSMT (FKVB + 2 * FSTG)        // Q + 2 stages = 92160 B

// ---------------- scratch (device globals; no allocations allowed) ----------
__device__ float g_h[SQ * HD];                 // fp32 residual stream
__device__ __half g_lnb16[SQ * HD];
__device__ __half g_qkv16[SQ * 3 * HD];
__device__ __half g_ctx16[SQ * HD];
__device__ __half g_fc16[SQ * 4 * HD];
// fp16 transposed weights [N,K]
__device__ __half g_qkvwT[NLAYER * 3 * HD * HD];
__device__ __half g_densewT[NLAYER * HD * HD];
__device__ __half g_fcwT[NLAYER * 4 * HD * HD];
__device__ __half g_projwT[NLAYER * 4 * HD * HD];

// ---------------- helpers ----------------------------------------------------
__device__ __forceinline__ float gelu_f(float x) {
    return 0.5f * x * (1.0f + tanhf(0.7978845608028654f * x * (1.0f + 0.044715f * x * x)));
}

__device__ __forceinline__ void cp16h(uint32_t smem, const __half* g) {
    asm volatile("cp.async.ca.shared.global [%0], [%1], 16;\n" :: "r"(smem), "l"(g));
}

__device__ __forceinline__ void ldsm4(uint32_t* r, uint32_t addr) {
    asm volatile("ldmatrix.sync.aligned.m8n8.x4.shared.b16 {%0,%1,%2,%3}, [%4];"
                 : "=r"(r[0]), "=r"(r[1]), "=r"(r[2]), "=r"(r[3]) : "r"(addr));
}

__device__ __forceinline__ void ldsm4t(uint32_t* r, uint32_t addr) {
    asm volatile("ldmatrix.sync.aligned.m8n8.x4.trans.shared.b16 {%0,%1,%2,%3}, [%4];"
                 : "=r"(r[0]), "=r"(r[1]), "=r"(r[2]), "=r"(r[3]) : "r"(addr));
}

__device__ __forceinline__ void mma16(float* d, const uint32_t* a, const uint32_t* b) {
    asm volatile(
        "mma.sync.aligned.m16n8k16.row.col.f32.f16.f16.f32 "
        "{%0,%1,%2,%3}, {%4,%5,%6,%7}, {%8,%9}, {%0,%1,%2,%3};\n"
        : "+f"(d[0]), "+f"(d[1]), "+f"(d[2]), "+f"(d[3])
        : "r"(a[0]), "r"(a[1]), "r"(a[2]), "r"(a[3]), "r"(b[0]), "r"(b[1]));
}

__device__ __forceinline__ uint32_t packh2(float a, float b) {
    __half2 h = __floats2half2_rn(a, b);
    return *(uint32_t*)&h;
}

// ---------------- layernorm ---------------------------------------------------
template <typename OUT>
__global__ __launch_bounds__(256) void ln_kernel(const float* __restrict__ x,
                                                 const float* __restrict__ g,
                                                 const float* __restrict__ b,
                                                 OUT* __restrict__ out) {
    int row = blockIdx.x;
    const float* xr = x + (size_t)row * HD;
    OUT* outr = out + (size_t)row * HD;
    __shared__ float red[256];
    int t = threadIdx.x;

    float s = 0.0f;
    for (int i = t; i < HD; i += 256) s += xr[i];
    red[t] = s;
    __syncthreads();
    for (int o = 128; o > 0; o >>= 1) {
        if (t < o) red[t] += red[t + o];
        __syncthreads();
    }
    float mu = red[0] * (1.0f / HD);
    __syncthreads();

    float v = 0.0f;
    for (int i = t; i < HD; i += 256) {
        float d = xr[i] - mu;
        v += d * d;
    }
    red[t] = v;
    __syncthreads();
    for (int o = 128; o > 0; o >>= 1) {
        if (t < o) red[t] += red[t + o];
        __syncthreads();
    }
    float rstd = rsqrtf(red[0] * (1.0f / HD) + 1e-5f);

    for (int i = t; i < HD; i += 256)
        outr[i] = (OUT)((xr[i] - mu) * rstd * g[i] + b[i]);
}

// ---------------- weight transpose+convert: W[K,N] fp32 -> Wt[N,K] fp16 ------
__global__ void transpose_w_h(const float* __restrict__ W, __half* __restrict__ Wt,
                              int Kd, int Nd) {
    __shared__ float tile[32][33];
    long long zo = (long long)blockIdx.z * Kd * Nd;
    int n0 = blockIdx.x * 32, k0 = blockIdx.y * 32;
    int tx = threadIdx.x, ty = threadIdx.y;
#pragma unroll
    for (int i = 0; i < 32; i += 8)
        tile[ty + i][tx] = W[zo + (long long)(k0 + ty + i) * Nd + n0 + tx];
    __syncthreads();
#pragma unroll
    for (int i = 0; i < 32; i += 8)
        Wt[zo + (long long)(n0 + ty + i) * Kd + k0 + tx] = __float2half(tile[tx][ty + i]);
}

// ---------------- fused flash attention ---------------------------------------
// grid: (SQ/128, NHEAD), block 256 (8 warps x 16 q-rows). KV tile = 128 keys.
// Online softmax in registers; P reused as mma A-frags; V via ldmatrix.trans.
__global__ __launch_bounds__(256, 1) void flash_attn(
    const __half* __restrict__ qkv, __half* __restrict__ ctx) {
    extern __shared__ __align__(16) char fsm[];
    uint32_t sb;
    asm("{ .reg .u64 tmp; cvta.to.shared.u64 tmp, %1; cvt.u32.u64 %0, tmp; }"
        : "=r"(sb) : "l"(fsm));

    int qt = gridDim.x - 1 - blockIdx.x;   // heavy q-tiles first
    int hh = blockIdx.y;
    int ntiles = qt + 1;

    int t = threadIdx.x, w = t >> 5, lane = t & 31;
    int lrow = lane & 15, lcol = (lane >> 4) << 3;
    int g = lane >> 2, tig = lane & 3;

    const __half* Qg = qkv + (size_t)(qt * 128) * (3 * HD) + hh * HNDIM;
    const __half* Kg = qkv + HD + hh * HNDIM;
    const __half* Vg = qkv + 2 * HD + hh * HNDIM;

    // 128 rows x 64 halves per tile: 1024 slots of 8 halves = 4 iters x 256 thr
#define FLOADKV(j)                                                                 \
    {                                                                              \
        uint32_t base_ = sb + FKVB + ((j) & 1) * FSTG;                             \
        const __half* Kg_ = Kg + (size_t)((j) * 128) * (3 * HD);                   \
        const __half* Vg_ = Vg + (size_t)((j) * 128) * (3 * HD);                   \
        _Pragma("unroll") for (int i_ = 0; i_ < 4; i_++) {                         \
            int id_ = t + i_ * 256;                                                \
            int r_ = id_ >> 3, c_ = (id_ & 7) * 8;                                 \
            cp16h(base_ + (r_ * FLDQ + c_) * 2, Kg_ + (size_t)r_ * (3 * HD) + c_); \
            cp16h(base_ + FKVB + (r_ * FLDQ + c_) * 2,                             \
                  Vg_ + (size_t)r_ * (3 * HD) + c_);                               \
        }                                                                          \
        asm volatile("cp.async.commit_group;\n" ::: "memory");                     \
    }

    // group 0: Q + KV tile 0
#pragma unroll
    for (int i = 0; i < 4; i++) {
        int id = t + i * 256;
        int r = id >> 3, c = (id & 7) * 8;
        cp16h(sb + (r * FLDQ + c) * 2, Qg + (size_t)r * (3 * HD) + c);
    }
    FLOADKV(0);
    int issued = 1;
    if (ntiles > 1) { FLOADKV(1); issued = 2; }

    float m0 = -1e30f, m1 = -1e30f, l0 = 0.0f, l1 = 0.0f;
    float out[8][4] = {};
    uint32_t aq[4][4];

    int row0 = qt * 128 + w * 16 + g;
    int row1 = row0 + 8;

    for (int j = 0; j < ntiles; j++) {
        if (issued > j + 1) asm volatile("cp.async.wait_group 1;\n" ::: "memory");
        else asm volatile("cp.async.wait_group 0;\n" ::: "memory");
        __syncthreads();

        if (j == 0) {
#pragma unroll
            for (int kk = 0; kk < 4; kk++)
                ldsm4(aq[kk], sb + ((w * 16 + lrow) * FLDQ + kk * 16 + lcol) * 2);
        }

        uint32_t kb = sb + FKVB + (j & 1) * FSTG;
        uint32_t vb = kb + FKVB;

        // S = Q K^T  (128 keys -> 16 n8 frags)
        float sacc[16][4] = {};
#pragma unroll
        for (int kk = 0; kk < 4; kk++) {
            uint32_t bk[16][2];
#pragma unroll
            for (int jp = 0; jp < 8; jp++) {
                uint32_t r4[4];
                ldsm4(r4, kb + ((jp * 16 + lrow) * FLDQ + kk * 16 + lcol) * 2);
                bk[2 * jp][0] = r4[0]; bk[2 * jp][1] = r4[2];
                bk[2 * jp + 1][0] = r4[1]; bk[2 * jp + 1][1] = r4[3];
            }
#pragma unroll
            for (int jn = 0; jn < 16; jn++) mma16(sacc[jn], aq[kk], bk[jn]);
        }

        // scale + causal mask + tile row-max
        bool diag = (j == qt);
        float tm0 = -1e30f, tm1 = -1e30f;
#pragma unroll
        for (int jn = 0; jn < 16; jn++) {
            int col = j * 128 + jn * 8 + tig * 2;
            float s0 = sacc[jn][0] * 0.125f, s1 = sacc[jn][1] * 0.125f;
            float s2 = sacc[jn][2] * 0.125f, s3 = sacc[jn][3] * 0.125f;
            if (diag) {
                if (col > row0) s0 = -10000.0f;
                if (col + 1 > row0) s1 = -10000.0f;
                if (col > row1) s2 = -10000.0f;
                if (col + 1 > row1) s3 = -10000.0f;
            }
            sacc[jn][0] = s0; sacc[jn][1] = s1; sacc[jn][2] = s2; sacc[jn][3] = s3;
            tm0 = fmaxf(tm0, fmaxf(s0, s1));
            tm1 = fmaxf(tm1, fmaxf(s2, s3));
        }
        tm0 = fmaxf(tm0, __shfl_xor_sync(~0u, tm0, 1));
        tm0 = fmaxf(tm0, __shfl_xor_sync(~0u, tm0, 2));
        tm1 = fmaxf(tm1, __shfl_xor_sync(~0u, tm1, 1));
        tm1 = fmaxf(tm1, __shfl_xor_sync(~0u, tm1, 2));

        float mn0 = fmaxf(m0, tm0), mn1 = fmaxf(m1, tm1);
        float c0 = __expf(m0 - mn0), c1 = __expf(m1 - mn1);
        l0 *= c0; l1 *= c1;
#pragma unroll
        for (int jo = 0; jo < 8; jo++) {
            out[jo][0] *= c0; out[jo][1] *= c0;
            out[jo][2] *= c1; out[jo][3] *= c1;
        }
        m0 = mn0; m1 = mn1;

        // P = exp(S - m) -> fp16 A-frags (C-frag -> A-frag identity)
        uint32_t pa[8][4];
#pragma unroll
        for (int kk2 = 0; kk2 < 8; kk2++) {
            float p00 = __expf(sacc[2 * kk2][0] - mn0);
            float p01 = __expf(sacc[2 * kk2][1] - mn0);
            float p02 = __expf(sacc[2 * kk2][2] - mn1);
            float p03 = __expf(sacc[2 * kk2][3] - mn1);
            float p10 = __expf(sacc[2 * kk2 + 1][0] - mn0);
            float p11 = __expf(sacc[2 * kk2 + 1][1] - mn0);
            float p12 = __expf(sacc[2 * kk2 + 1][2] - mn1);
            float p13 = __expf(sacc[2 * kk2 + 1][3] - mn1);
            l0 += p00 + p01 + p10 + p11;
            l1 += p02 + p03 + p12 + p13;
            pa[kk2][0] = packh2(p00, p01);
            pa[kk2][1] = packh2(p02, p03);
            pa[kk2][2] = packh2(p10, p11);
            pa[kk2][3] = packh2(p12, p13);
        }

        // out += P V   (V via ldmatrix.trans from [s][d])
#pragma unroll
        for (int kk2 = 0; kk2 < 8; kk2++) {
            uint32_t bv[8][2];
#pragma unroll
            for (int jp = 0; jp < 4; jp++) {
                uint32_t r4[4];
                ldsm4t(r4, vb + ((kk2 * 16 + lrow) * FLDQ + jp * 16 + lcol) * 2);
                bv[2 * jp][0] = r4[0]; bv[2 * jp][1] = r4[1];
                bv[2 * jp + 1][0] = r4[2]; bv[2 * jp + 1][1] = r4[3];
            }
#pragma unroll
            for (int jo = 0; jo < 8; jo++) mma16(out[jo], pa[kk2], bv[jo]);
        }

        __syncthreads();   // all warps done reading stage j
        if (j + 2 < ntiles) { FLOADKV(j + 2); issued++; }
    }
#undef FLOADKV

    // finalize: full row sums, normalize, write ctx
    l0 += __shfl_xor_sync(~0u, l0, 1);
    l0 += __shfl_xor_sync(~0u, l0, 2);
    l1 += __shfl_xor_sync(~0u, l1, 1);
    l1 += __shfl_xor_sync(~0u, l1, 2);
    float r0 = 1.0f / l0, r1 = 1.0f / l1;

#pragma unroll
    for (int jo = 0; jo < 8; jo++) {
        int d = hh * HNDIM + jo * 8 + tig * 2;
        __half2 o0 = __floats2half2_rn(out[jo][0] * r0, out[jo][1] * r0);
        __half2 o1 = __floats2half2_rn(out[jo][2] * r1, out[jo][3] * r1);
        *(__half2*)(ctx + (size_t)row0 * HD + d) = o0;
        *(__half2*)(ctx + (size_t)row1 * HD + d) = o1;
    }
}

// ---------------- fp16 tensor-core GEMM (linear layers) -----------------------
template <int TBN, int OUTH>
__global__ __launch_bounds__(256, 2) void hgemm(
    const __half* __restrict__ A, int lda, long long hsA,
    const __half* __restrict__ B, int ldb, long long hsB,
    const float* __restrict__ bias,
    const float* __restrict__ R,
    void* __restrict__ Cv, int ldc, long long hsC,
    int K, int act) {
    constexpr int NF = TBN / 16;
    constexpr int ASZ = BM * LDK * 2;
    constexpr int BSZ = TBN * LDK * 2;
    constexpr int STB = ASZ + BSZ;
    constexpr int B_CP = (TBN * BK / 8) / 256;

    extern __shared__ __align__(16) char smem[];
    uint32_t sb;
    asm("{ .reg .u64 tmp; cvta.to.shared.u64 tmp, %1; cvt.u32.u64 %0, tmp; }"
        : "=r"(sb) : "l"(smem));

    int m0 = blockIdx.y * BM;
    int n0 = blockIdx.x * TBN;

    A += (long long)blockIdx.z * hsA;
    B += (long long)blockIdx.z * hsB;

    int T = K / BK;

    int t = threadIdx.x;
    int wid = t >> 5, lane = t & 31;
    int g = lane >> 2, tig = lane & 3;
    int wm = (wid & 3) * 32;
    int wn = (wid >> 2) * (TBN / 2);

    const __half* Ag0 = A + (long long)m0 * lda;
    const __half* Bg0 = B + (long long)n0 * ldb;

    float acc[2][NF][4] = {};

#define LOADST(ti)                                                                \
    {                                                                             \
        uint32_t as_ = sb + ((ti) % NST) * STB;                                   \
        uint32_t bs_ = as_ + ASZ;                                                 \
        const __half* Ag_ = Ag0 + (long long)(ti) * BK;                           \
        const __half* Bg_ = Bg0 + (long long)(ti) * BK;                           \
        _Pragma("unroll") for (int i = 0; i < 2; i++) {                           \
            int id = t + i * 256;                                                 \
            int r = id >> 2, c = (id & 3) * 8;                                    \
            cp16h(as_ + (r * LDK + c) * 2, Ag_ + (long long)r * lda + c);         \
        }                                                                         \
        _Pragma("unroll") for (int i = 0; i < B_CP; i++) {                        \
            int id = t + i * 256;                                                 \
            int r = id >> 2, c = (id & 3) * 8;                                    \
            cp16h(bs_ + (r * LDK + c) * 2, Bg_ + (long long)r * ldb + c);         \
        }                                                                         \
        asm volatile("cp.async.commit_group;\n" ::: "memory");                    \
    }

    int loaded = 0;
    for (; loaded < 2 && loaded < T; loaded++) LOADST(loaded);

    int lrow = lane & 15, lcol = (lane >> 4) << 3;

    for (int ti = 0; ti < T; ti++) {
        if (loaded - ti >= 2) asm volatile("cp.async.wait_group 1;\n" ::: "memory");
        else asm volatile("cp.async.wait_group 0;\n" ::: "memory");
        __syncthreads();
        if (loaded < T) { LOADST(loaded); loaded++; }

        uint32_t as = sb + (ti % NST) * STB;
        uint32_t bs = as + ASZ;

#pragma unroll
        for (int kk = 0; kk < 2; kk++) {
            int k16 = kk * 16;
            uint32_t a[2][4];
#pragma unroll
            for (int f = 0; f < 2; f++)
                ldsm4(a[f], as + ((wm + f * 16 + lrow) * LDK + k16 + lcol) * 2);
            uint32_t bf[NF][2];
#pragma unroll
            for (int jp = 0; jp < NF / 2; jp++) {
                uint32_t r4[4];
                ldsm4(r4, bs + ((wn + jp * 16 + lrow) * LDK + k16 + lcol) * 2);
                bf[2 * jp][0] = r4[0]; bf[2 * jp][1] = r4[2];
                bf[2 * jp + 1][0] = r4[1]; bf[2 * jp + 1][1] = r4[3];
            }
#pragma unroll
            for (int f = 0; f < 2; f++)
#pragma unroll
                for (int j = 0; j < NF; j++) mma16(acc[f][j], a[f], bf[j]);
        }
    }
#undef LOADST

    long long co = (long long)blockIdx.z * hsC;
#pragma unroll
    for (int f = 0; f < 2; f++) {
#pragma unroll
        for (int j = 0; j < NF; j++) {
            int n = n0 + wn + j * 8 + tig * 2;
#pragma unroll
            for (int half_ = 0; half_ < 2; half_++) {
                int m = m0 + wm + f * 16 + g + half_ * 8;
                float v0 = acc[f][j][half_ * 2 + 0];
                float v1 = acc[f][j][half_ * 2 + 1];
                if (bias) {
                    float2 bb = *(const float2*)(bias + n);
                    v0 += bb.x; v1 += bb.y;
                }
                if (act) { v0 = gelu_f(v0); v1 = gelu_f(v1); }
                if (R) {
                    float2 rr = *(const float2*)(R + co + (long long)m * ldc + n);
                    v0 += rr.x; v1 += rr.y;
                }
                if (OUTH) {
                    __half2* outp = (__half2*)((__half*)Cv + co + (long long)m * ldc + n);
                    *outp = __floats2half2_rn(v0, v1);
                } else {
                    float2* outp = (float2*)((float*)Cv + co + (long long)m * ldc + n);
                    *outp = make_float2(v0, v1);
                }
            }
        }
    }
}

// ---------------- host orchestration ------------------------------------------
extern "C" void kernel_launch(void* const* d_in, const int* in_sizes, int n_in,
                              void* d_out, int out_size) {
    const float* x = (const float*)d_in[0];
    const float* ln1_g = (const float*)d_in[2];
    const float* ln1_b = (const float*)d_in[3];
    const float* qkv_w = (const float*)d_in[4];
    const float* qkv_b = (const float*)d_in[5];
    const float* dense_w = (const float*)d_in[6];
    const float* dense_b = (const float*)d_in[7];
    const float* ln2_g = (const float*)d_in[8];
    const float* ln2_b = (const float*)d_in[9];
    const float* fc_w = (const float*)d_in[10];
    const float* fc_b = (const float*)d_in[11];
    const float* proj_w = (const float*)d_in[12];
    const float* proj_b = (const float*)d_in[13];
    const float* lnf_g = (const float*)d_in[14];
    const float* lnf_b = (const float*)d_in[15];

    float* h;
    __half *lnb16, *qkv16, *ctx16, *fc16;
    __half *qkvwT, *densewT, *fcwT, *projwT;
    cudaGetSymbolAddress((void**)&h, g_h);
    cudaGetSymbolAddress((void**)&lnb16, g_lnb16);
    cudaGetSymbolAddress((void**)&qkv16, g_qkv16);
    cudaGetSymbolAddress((void**)&ctx16, g_ctx16);
    cudaGetSymbolAddress((void**)&fc16, g_fc16);
    cudaGetSymbolAddress((void**)&qkvwT, g_qkvwT);
    cudaGetSymbolAddress((void**)&densewT, g_densewT);
    cudaGetSymbolAddress((void**)&fcwT, g_fcwT);
    cudaGetSymbolAddress((void**)&projwT, g_projwT);

    const int SMH128 = NST * (BM * LDK * 2 + 128 * LDK * 2);  // 61440
    cudaFuncSetAttribute(hgemm<128, 0>, cudaFuncAttributeMaxDynamicSharedMemorySize, SMH128);
    cudaFuncSetAttribute(hgemm<128, 1>, cudaFuncAttributeMaxDynamicSharedMemorySize, SMH128);
    cudaFuncSetAttribute(flash_attn, cudaFuncAttributeMaxDynamicSharedMemorySize, FSMT);

    cudaMemcpyAsync(h, x, sizeof(float) * SQ * HD, cudaMemcpyDeviceToDevice, 0);

    transpose_w_h<<<dim3(3 * HD / 32, HD / 32, NLAYER), dim3(32, 8)>>>(qkv_w, qkvwT, HD, 3 * HD);
    transpose_w_h<<<dim3(HD / 32, HD / 32, NLAYER), dim3(32, 8)>>>(dense_w, densewT, HD, HD);
    transpose_w_h<<<dim3(4 * HD / 32, HD / 32, NLAYER), dim3(32, 8)>>>(fc_w, fcwT, HD, 4 * HD);
    transpose_w_h<<<dim3(HD / 32, 4 * HD / 32, NLAYER), dim3(32, 8)>>>(proj_w, projwT, 4 * HD, HD);

    for (int l = 0; l < NLAYER; l++) {
        // LN1 -> fp16
        ln_kernel<__half><<<SQ, 256>>>(h, ln1_g + l * HD, ln1_b + l * HD, lnb16);
        // QKV
        hgemm<128, 1><<<dim3(3 * HD / 128, SQ / BM), 256, SMH128>>>(
            lnb16, HD, 0, qkvwT + (long long)l * 3 * HD * HD, HD, 0,
            qkv_b + l * 3 * HD, nullptr, qkv16, 3 * HD, 0, HD, 0);
        // fused attention: scores + softmax + PV -> ctx16
        flash_attn<<<dim3(SQ / 128, NHEAD), 256, FSMT>>>(qkv16, ctx16);
        // dense + residual -> fp32 h
        hgemm<128, 0><<<dim3(HD / 128, SQ / BM), 256, SMH128>>>(
            ctx16, HD, 0, densewT + (long long)l * HD * HD, HD, 0,
            dense_b + l * HD, h, h, HD, 0, HD, 0);
        // LN2 -> fp16
        ln_kernel<__half><<<SQ, 256>>>(h, ln2_g + l * HD, ln2_b + l * HD, lnb16);
        // FC + gelu -> fp16
        hgemm<128, 1><<<dim3(4 * HD / 128, SQ / BM), 256, SMH128>>>(
            lnb16, HD, 0, fcwT + (long long)l * 4 * HD * HD, HD, 0,
            fc_b + l * 4 * HD, nullptr, fc16, 4 * HD, 0, HD, 1);
        // proj + residual -> fp32 h
        hgemm<128, 0><<<dim3(HD / 128, SQ / BM), 256, SMH128>>>(
            fc16, 4 * HD, 0, projwT + (long long)l * 4 * HD * HD, 4 * HD, 0,
            proj_b + l * HD, h, h, HD, 0, 4 * HD, 0);
    }
    ln_kernel<float><<<SQ, 256>>>(h, lnf_g, lnf_b, (float*)d_out);
}

// round 8
// speedup vs baseline: 9.4261x; 1.1833x over previous
#include <cuda_runtime.h>
#include <cuda_fp16.h>
#include <math.h>
#include <stdint.h>

#define SQ 2048
#define HD 1024
#define NHEAD 16
#define HNDIM 64
#define NLAYER 2

#define BM 128
#define BK 64      // halves per K-tile (GEMM)
#define LDK 72     // padded GEMM smem row (halves) -> 144B stride, LDSM conflict-free
#define NST 2      // GEMM pipeline stages

// flash attention tiles
#define FLDQ 72                       // padded row length (halves) for Q/K/V tiles
#define FKVB (128 * FLDQ * 2)         // bytes per 128x64 tile = 18432
#define FSTG (2 * FKVB)               // K+V per stage
#define FSMT (FKVB + 2 * FSTG)        // Q + 2 stages = 92160 B

// ---------------- scratch (device globals; no allocations allowed) ----------
__device__ float g_h[SQ * HD];                 // fp32 residual stream
__device__ __half g_lnb16[SQ * HD];
__device__ __half g_qkv16[SQ * 3 * HD];
__device__ __half g_ctx16[SQ * HD];
__device__ __half g_fc16[SQ * 4 * HD];
// fp16 transposed weights [N,K]
__device__ __half g_qkvwT[NLAYER * 3 * HD * HD];
__device__ __half g_densewT[NLAYER * HD * HD];
__device__ __half g_fcwT[NLAYER * 4 * HD * HD];
__device__ __half g_projwT[NLAYER * 4 * HD * HD];

// ---------------- helpers ----------------------------------------------------
__device__ __forceinline__ float gelu_f(float x) {
    return 0.5f * x * (1.0f + tanhf(0.7978845608028654f * x * (1.0f + 0.044715f * x * x)));
}

__device__ __forceinline__ void cp16h(uint32_t smem, const __half* g) {
    asm volatile("cp.async.ca.shared.global [%0], [%1], 16;\n" :: "r"(smem), "l"(g));
}

__device__ __forceinline__ void ldsm4(uint32_t* r, uint32_t addr) {
    asm volatile("ldmatrix.sync.aligned.m8n8.x4.shared.b16 {%0,%1,%2,%3}, [%4];"
                 : "=r"(r[0]), "=r"(r[1]), "=r"(r[2]), "=r"(r[3]) : "r"(addr));
}

__device__ __forceinline__ void ldsm4t(uint32_t* r, uint32_t addr) {
    asm volatile("ldmatrix.sync.aligned.m8n8.x4.trans.shared.b16 {%0,%1,%2,%3}, [%4];"
                 : "=r"(r[0]), "=r"(r[1]), "=r"(r[2]), "=r"(r[3]) : "r"(addr));
}

__device__ __forceinline__ void mma16(float* d, const uint32_t* a, const uint32_t* b) {
    asm volatile(
        "mma.sync.aligned.m16n8k16.row.col.f32.f16.f16.f32 "
        "{%0,%1,%2,%3}, {%4,%5,%6,%7}, {%8,%9}, {%0,%1,%2,%3};\n"
        : "+f"(d[0]), "+f"(d[1]), "+f"(d[2]), "+f"(d[3])
        : "r"(a[0]), "r"(a[1]), "r"(a[2]), "r"(a[3]), "r"(b[0]), "r"(b[1]));
}

__device__ __forceinline__ uint32_t packh2(float a, float b) {
    __half2 h = __floats2half2_rn(a, b);
    return *(uint32_t*)&h;
}

// ---------------- layernorm: one-pass (E[x^2]-mu^2), shuffle reduce -----------
template <typename OUT>
__global__ __launch_bounds__(256) void ln_kernel(const float* __restrict__ x,
                                                 const float* __restrict__ g,
                                                 const float* __restrict__ b,
                                                 OUT* __restrict__ out) {
    int row = blockIdx.x;
    const float* xr = x + (size_t)row * HD;
    OUT* outr = out + (size_t)row * HD;
    int t = threadIdx.x;
    __shared__ float red1[8], red2[8];

    float v[4];
    float s1 = 0.0f, s2 = 0.0f;
#pragma unroll
    for (int j = 0; j < 4; j++) {
        v[j] = xr[t + j * 256];
        s1 += v[j];
        s2 += v[j] * v[j];
    }
#pragma unroll
    for (int o = 16; o > 0; o >>= 1) {
        s1 += __shfl_xor_sync(~0u, s1, o);
        s2 += __shfl_xor_sync(~0u, s2, o);
    }
    if ((t & 31) == 0) { red1[t >> 5] = s1; red2[t >> 5] = s2; }
    __syncthreads();
    s1 = 0.0f; s2 = 0.0f;
#pragma unroll
    for (int w = 0; w < 8; w++) { s1 += red1[w]; s2 += red2[w]; }
    float mu = s1 * (1.0f / HD);
    float var = s2 * (1.0f / HD) - mu * mu;
    float rstd = rsqrtf(var + 1e-5f);

#pragma unroll
    for (int j = 0; j < 4; j++) {
        int i = t + j * 256;
        outr[i] = (OUT)((v[j] - mu) * rstd * g[i] + b[i]);
    }
}

// ---------------- weight transpose+convert: W[K,N] fp32 -> Wt[N,K] fp16 ------
__global__ void transpose_w_h(const float* __restrict__ W, __half* __restrict__ Wt,
                              int Kd, int Nd) {
    __shared__ float tile[32][33];
    long long zo = (long long)blockIdx.z * Kd * Nd;
    int n0 = blockIdx.x * 32, k0 = blockIdx.y * 32;
    int tx = threadIdx.x, ty = threadIdx.y;
#pragma unroll
    for (int i = 0; i < 32; i += 8)
        tile[ty + i][tx] = W[zo + (long long)(k0 + ty + i) * Nd + n0 + tx];
    __syncthreads();
#pragma unroll
    for (int i = 0; i < 32; i += 8)
        Wt[zo + (long long)(n0 + ty + i) * Kd + k0 + tx] = __float2half(tile[tx][ty + i]);
}

// ---------------- fused flash attention ---------------------------------------
// grid: (SQ/128, NHEAD), block 256 (8 warps x 16 q-rows). KV tile = 128 keys.
// 2-stage, ONE __syncthreads per KV tile.
__global__ __launch_bounds__(256, 1) void flash_attn(
    const __half* __restrict__ qkv, __half* __restrict__ ctx) {
    extern __shared__ __align__(16) char fsm[];
    uint32_t sb;
    asm("{ .reg .u64 tmp; cvta.to.shared.u64 tmp, %1; cvt.u32.u64 %0, tmp; }"
        : "=r"(sb) : "l"(fsm));

    int qt = gridDim.x - 1 - blockIdx.x;   // heavy q-tiles first
    int hh = blockIdx.y;
    int ntiles = qt + 1;

    int t = threadIdx.x, w = t >> 5, lane = t & 31;
    int lrow = lane & 15, lcol = (lane >> 4) << 3;
    int g = lane >> 2, tig = lane & 3;

    const __half* Qg = qkv + (size_t)(qt * 128) * (3 * HD) + hh * HNDIM;
    const __half* Kg = qkv + HD + hh * HNDIM;
    const __half* Vg = qkv + 2 * HD + hh * HNDIM;

#define FLOADKV(j)                                                                 \
    {                                                                              \
        uint32_t base_ = sb + FKVB + ((j) & 1) * FSTG;                             \
        const __half* Kg_ = Kg + (size_t)((j) * 128) * (3 * HD);                   \
        const __half* Vg_ = Vg + (size_t)((j) * 128) * (3 * HD);                   \
        _Pragma("unroll") for (int i_ = 0; i_ < 4; i_++) {                         \
            int id_ = t + i_ * 256;                                                \
            int r_ = id_ >> 3, c_ = (id_ & 7) * 8;                                 \
            cp16h(base_ + (r_ * FLDQ + c_) * 2, Kg_ + (size_t)r_ * (3 * HD) + c_); \
            cp16h(base_ + FKVB + (r_ * FLDQ + c_) * 2,                             \
                  Vg_ + (size_t)r_ * (3 * HD) + c_);                               \
        }                                                                          \
        asm volatile("cp.async.commit_group;\n" ::: "memory");                     \
    }

    // group 0: Q + KV tile 0
#pragma unroll
    for (int i = 0; i < 4; i++) {
        int id = t + i * 256;
        int r = id >> 3, c = (id & 7) * 8;
        cp16h(sb + (r * FLDQ + c) * 2, Qg + (size_t)r * (3 * HD) + c);
    }
    FLOADKV(0);

    float m0 = -1e30f, m1 = -1e30f, l0 = 0.0f, l1 = 0.0f;
    float out[8][4] = {};
    uint32_t aq[4][4];

    int row0 = qt * 128 + w * 16 + g;
    int row1 = row0 + 8;

    for (int j = 0; j < ntiles; j++) {
        asm volatile("cp.async.wait_group 0;\n" ::: "memory");
        __syncthreads();   // publishes stage j; frees stage j-1 for prefetch
        if (j + 1 < ntiles) FLOADKV(j + 1);

        if (j == 0) {
#pragma unroll
            for (int kk = 0; kk < 4; kk++)
                ldsm4(aq[kk], sb + ((w * 16 + lrow) * FLDQ + kk * 16 + lcol) * 2);
        }

        uint32_t kb = sb + FKVB + (j & 1) * FSTG;
        uint32_t vb = kb + FKVB;

        // S = Q K^T  (128 keys -> 16 n8 frags)
        float sacc[16][4] = {};
#pragma unroll
        for (int kk = 0; kk < 4; kk++) {
            uint32_t bk[16][2];
#pragma unroll
            for (int jp = 0; jp < 8; jp++) {
                uint32_t r4[4];
                ldsm4(r4, kb + ((jp * 16 + lrow) * FLDQ + kk * 16 + lcol) * 2);
                bk[2 * jp][0] = r4[0]; bk[2 * jp][1] = r4[2];
                bk[2 * jp + 1][0] = r4[1]; bk[2 * jp + 1][1] = r4[3];
            }
#pragma unroll
            for (int jn = 0; jn < 16; jn++) mma16(sacc[jn], aq[kk], bk[jn]);
        }

        // scale + causal mask + tile row-max
        bool diag = (j == qt);
        float tm0 = -1e30f, tm1 = -1e30f;
#pragma unroll
        for (int jn = 0; jn < 16; jn++) {
            int col = j * 128 + jn * 8 + tig * 2;
            float s0 = sacc[jn][0] * 0.125f, s1 = sacc[jn][1] * 0.125f;
            float s2 = sacc[jn][2] * 0.125f, s3 = sacc[jn][3] * 0.125f;
            if (diag) {
                if (col > row0) s0 = -10000.0f;
                if (col + 1 > row0) s1 = -10000.0f;
                if (col > row1) s2 = -10000.0f;
                if (col + 1 > row1) s3 = -10000.0f;
            }
            sacc[jn][0] = s0; sacc[jn][1] = s1; sacc[jn][2] = s2; sacc[jn][3] = s3;
            tm0 = fmaxf(tm0, fmaxf(s0, s1));
            tm1 = fmaxf(tm1, fmaxf(s2, s3));
        }
        tm0 = fmaxf(tm0, __shfl_xor_sync(~0u, tm0, 1));
        tm0 = fmaxf(tm0, __shfl_xor_sync(~0u, tm0, 2));
        tm1 = fmaxf(tm1, __shfl_xor_sync(~0u, tm1, 1));
        tm1 = fmaxf(tm1, __shfl_xor_sync(~0u, tm1, 2));

        float mn0 = fmaxf(m0, tm0), mn1 = fmaxf(m1, tm1);
        float c0 = __expf(m0 - mn0), c1 = __expf(m1 - mn1);
        l0 *= c0; l1 *= c1;
#pragma unroll
        for (int jo = 0; jo < 8; jo++) {
            out[jo][0] *= c0; out[jo][1] *= c0;
            out[jo][2] *= c1; out[jo][3] *= c1;
        }
        m0 = mn0; m1 = mn1;

        // P = exp(S - m) -> fp16 A-frags
        uint32_t pa[8][4];
#pragma unroll
        for (int kk2 = 0; kk2 < 8; kk2++) {
            float p00 = __expf(sacc[2 * kk2][0] - mn0);
            float p01 = __expf(sacc[2 * kk2][1] - mn0);
            float p02 = __expf(sacc[2 * kk2][2] - mn1);
            float p03 = __expf(sacc[2 * kk2][3] - mn1);
            float p10 = __expf(sacc[2 * kk2 + 1][0] - mn0);
            float p11 = __expf(sacc[2 * kk2 + 1][1] - mn0);
            float p12 = __expf(sacc[2 * kk2 + 1][2] - mn1);
            float p13 = __expf(sacc[2 * kk2 + 1][3] - mn1);
            l0 += p00 + p01 + p10 + p11;
            l1 += p02 + p03 + p12 + p13;
            pa[kk2][0] = packh2(p00, p01);
            pa[kk2][1] = packh2(p02, p03);
            pa[kk2][2] = packh2(p10, p11);
            pa[kk2][3] = packh2(p12, p13);
        }

        // out += P V   (V via ldmatrix.trans from [s][d])
#pragma unroll
        for (int kk2 = 0; kk2 < 8; kk2++) {
            uint32_t bv[8][2];
#pragma unroll
            for (int jp = 0; jp < 4; jp++) {
                uint32_t r4[4];
                ldsm4t(r4, vb + ((kk2 * 16 + lrow) * FLDQ + jp * 16 + lcol) * 2);
                bv[2 * jp][0] = r4[0]; bv[2 * jp][1] = r4[1];
                bv[2 * jp + 1][0] = r4[2]; bv[2 * jp + 1][1] = r4[3];
            }
#pragma unroll
            for (int jo = 0; jo < 8; jo++) mma16(out[jo], pa[kk2], bv[jo]);
        }
    }
#undef FLOADKV

    // finalize
    l0 += __shfl_xor_sync(~0u, l0, 1);
    l0 += __shfl_xor_sync(~0u, l0, 2);
    l1 += __shfl_xor_sync(~0u, l1, 1);
    l1 += __shfl_xor_sync(~0u, l1, 2);
    float r0 = 1.0f / l0, r1 = 1.0f / l1;

#pragma unroll
    for (int jo = 0; jo < 8; jo++) {
        int d = hh * HNDIM + jo * 8 + tig * 2;
        __half2 o0 = __floats2half2_rn(out[jo][0] * r0, out[jo][1] * r0);
        __half2 o1 = __floats2half2_rn(out[jo][2] * r1, out[jo][3] * r1);
        *(__half2*)(ctx + (size_t)row0 * HD + d) = o0;
        *(__half2*)(ctx + (size_t)row1 * HD + d) = o1;
    }
}

// ---------------- fp16 tensor-core GEMM (linear layers) -----------------------
// BK=64, 2-stage, ONE __syncthreads per K-tile. TBN=128 for all linear GEMMs.
template <int TBN, int OUTH>
__global__ __launch_bounds__(256, 2) void hgemm(
    const __half* __restrict__ A, int lda,
    const __half* __restrict__ B, int ldb,
    const float* __restrict__ bias,
    const float* __restrict__ R,
    void* __restrict__ Cv, int ldc,
    int K, int act) {
    constexpr int NF = TBN / 16;
    constexpr int ASZ = BM * LDK * 2;
    constexpr int BSZ = TBN * LDK * 2;
    constexpr int STB = ASZ + BSZ;
    constexpr int A_CP = (BM * BK / 8) / 256;   // 4
    constexpr int B_CP = (TBN * BK / 8) / 256;  // 4

    extern __shared__ __align__(16) char smem[];
    uint32_t sb;
    asm("{ .reg .u64 tmp; cvta.to.shared.u64 tmp, %1; cvt.u32.u64 %0, tmp; }"
        : "=r"(sb) : "l"(smem));

    int m0 = blockIdx.y * BM;
    int n0 = blockIdx.x * TBN;
    int T = K / BK;

    int t = threadIdx.x;
    int wid = t >> 5, lane = t & 31;
    int g = lane >> 2, tig = lane & 3;
    int wm = (wid & 3) * 32;
    int wn = (wid >> 2) * (TBN / 2);

    const __half* Ag0 = A + (long long)m0 * lda;
    const __half* Bg0 = B + (long long)n0 * ldb;

    float acc[2][NF][4] = {};

#define LOADST(ti)                                                                \
    {                                                                             \
        uint32_t as_ = sb + ((ti) & 1) * STB;                                     \
        uint32_t bs_ = as_ + ASZ;                                                 \
        const __half* Ag_ = Ag0 + (long long)(ti) * BK;                           \
        const __half* Bg_ = Bg0 + (long long)(ti) * BK;                           \
        _Pragma("unroll") for (int i = 0; i < A_CP; i++) {                        \
            int id = t + i * 256;                                                 \
            int r = id >> 3, c = (id & 7) * 8;                                    \
            cp16h(as_ + (r * LDK + c) * 2, Ag_ + (long long)r * lda + c);         \
        }                                                                         \
        _Pragma("unroll") for (int i = 0; i < B_CP; i++) {                        \
            int id = t + i * 256;                                                 \
            int r = id >> 3, c = (id & 7) * 8;                                    \
            cp16h(bs_ + (r * LDK + c) * 2, Bg_ + (long long)r * ldb + c);         \
        }                                                                         \
        asm volatile("cp.async.commit_group;\n" ::: "memory");                    \
    }

    LOADST(0);

    int lrow = lane & 15, lcol = (lane >> 4) << 3;

    for (int ti = 0; ti < T; ti++) {
        asm volatile("cp.async.wait_group 0;\n" ::: "memory");
        __syncthreads();   // publishes stage ti; frees stage ti-1
        if (ti + 1 < T) LOADST(ti + 1);

        uint32_t as = sb + (ti & 1) * STB;
        uint32_t bs = as + ASZ;

#pragma unroll
        for (int kk = 0; kk < 4; kk++) {
            int k16 = kk * 16;
            uint32_t a[2][4];
#pragma unroll
            for (int f = 0; f < 2; f++)
                ldsm4(a[f], as + ((wm + f * 16 + lrow) * LDK + k16 + lcol) * 2);
            uint32_t bf[NF][2];
#pragma unroll
            for (int jp = 0; jp < NF / 2; jp++) {
                uint32_t r4[4];
                ldsm4(r4, bs + ((wn + jp * 16 + lrow) * LDK + k16 + lcol) * 2);
                bf[2 * jp][0] = r4[0]; bf[2 * jp][1] = r4[2];
                bf[2 * jp + 1][0] = r4[1]; bf[2 * jp + 1][1] = r4[3];
            }
#pragma unroll
            for (int f = 0; f < 2; f++)
#pragma unroll
                for (int j = 0; j < NF; j++) mma16(acc[f][j], a[f], bf[j]);
        }
    }
#undef LOADST

#pragma unroll
    for (int f = 0; f < 2; f++) {
#pragma unroll
        for (int j = 0; j < NF; j++) {
            int n = n0 + wn + j * 8 + tig * 2;
#pragma unroll
            for (int half_ = 0; half_ < 2; half_++) {
                int m = m0 + wm + f * 16 + g + half_ * 8;
                float v0 = acc[f][j][half_ * 2 + 0];
                float v1 = acc[f][j][half_ * 2 + 1];
                if (bias) {
                    float2 bb = *(const float2*)(bias + n);
                    v0 += bb.x; v1 += bb.y;
                }
                if (act) { v0 = gelu_f(v0); v1 = gelu_f(v1); }
                if (R) {
                    float2 rr = *(const float2*)(R + (long long)m * ldc + n);
                    v0 += rr.x; v1 += rr.y;
                }
                if (OUTH) {
                    __half2* outp = (__half2*)((__half*)Cv + (long long)m * ldc + n);
                    *outp = __floats2half2_rn(v0, v1);
                } else {
                    float2* outp = (float2*)((float*)Cv + (long long)m * ldc + n);
                    *outp = make_float2(v0, v1);
                }
            }
        }
    }
}

// ---------------- host orchestration ------------------------------------------
extern "C" void kernel_launch(void* const* d_in, const int* in_sizes, int n_in,
                              void* d_out, int out_size) {
    const float* x = (const float*)d_in[0];
    const float* ln1_g = (const float*)d_in[2];
    const float* ln1_b = (const float*)d_in[3];
    const float* qkv_w = (const float*)d_in[4];
    const float* qkv_b = (const float*)d_in[5];
    const float* dense_w = (const float*)d_in[6];
    const float* dense_b = (const float*)d_in[7];
    const float* ln2_g = (const float*)d_in[8];
    const float* ln2_b = (const float*)d_in[9];
    const float* fc_w = (const float*)d_in[10];
    const float* fc_b = (const float*)d_in[11];
    const float* proj_w = (const float*)d_in[12];
    const float* proj_b = (const float*)d_in[13];
    const float* lnf_g = (const float*)d_in[14];
    const float* lnf_b = (const float*)d_in[15];

    float* h;
    __half *lnb16, *qkv16, *ctx16, *fc16;
    __half *qkvwT, *densewT, *fcwT, *projwT;
    cudaGetSymbolAddress((void**)&h, g_h);
    cudaGetSymbolAddress((void**)&lnb16, g_lnb16);
    cudaGetSymbolAddress((void**)&qkv16, g_qkv16);
    cudaGetSymbolAddress((void**)&ctx16, g_ctx16);
    cudaGetSymbolAddress((void**)&fc16, g_fc16);
    cudaGetSymbolAddress((void**)&qkvwT, g_qkvwT);
    cudaGetSymbolAddress((void**)&densewT, g_densewT);
    cudaGetSymbolAddress((void**)&fcwT, g_fcwT);
    cudaGetSymbolAddress((void**)&projwT, g_projwT);

    const int SMH = NST * (BM * LDK * 2 + 128 * LDK * 2);  // 73728
    cudaFuncSetAttribute(hgemm<128, 0>, cudaFuncAttributeMaxDynamicSharedMemorySize, SMH);
    cudaFuncSetAttribute(hgemm<128, 1>, cudaFuncAttributeMaxDynamicSharedMemorySize, SMH);
    cudaFuncSetAttribute(flash_attn, cudaFuncAttributeMaxDynamicSharedMemorySize, FSMT);

    cudaMemcpyAsync(h, x, sizeof(float) * SQ * HD, cudaMemcpyDeviceToDevice, 0);

    transpose_w_h<<<dim3(3 * HD / 32, HD / 32, NLAYER), dim3(32, 8)>>>(qkv_w, qkvwT, HD, 3 * HD);
    transpose_w_h<<<dim3(HD / 32, HD / 32, NLAYER), dim3(32, 8)>>>(dense_w, densewT, HD, HD);
    transpose_w_h<<<dim3(4 * HD / 32, HD / 32, NLAYER), dim3(32, 8)>>>(fc_w, fcwT, HD, 4 * HD);
    transpose_w_h<<<dim3(HD / 32, 4 * HD / 32, NLAYER), dim3(32, 8)>>>(proj_w, projwT, 4 * HD, HD);

    for (int l = 0; l < NLAYER; l++) {
        // LN1 -> fp16
        ln_kernel<__half><<<SQ, 256>>>(h, ln1_g + l * HD, ln1_b + l * HD, lnb16);
        // QKV
        hgemm<128, 1><<<dim3(3 * HD / 128, SQ / BM), 256, SMH>>>(
            lnb16, HD, qkvwT + (long long)l * 3 * HD * HD, HD,
            qkv_b + l * 3 * HD, nullptr, qkv16, 3 * HD, HD, 0);
        // fused attention
        flash_attn<<<dim3(SQ / 128, NHEAD), 256, FSMT>>>(qkv16, ctx16);
        // dense + residual -> fp32 h
        hgemm<128, 0><<<dim3(HD / 128, SQ / BM), 256, SMH>>>(
            ctx16, HD, densewT + (long long)l * HD * HD, HD,
            dense_b + l * HD, h, h, HD, HD, 0);
        // LN2 -> fp16
        ln_kernel<__half><<<SQ, 256>>>(h, ln2_g + l * HD, ln2_b + l * HD, lnb16);
        // FC + gelu -> fp16
        hgemm<128, 1><<<dim3(4 * HD / 128, SQ / BM), 256, SMH>>>(
            lnb16, HD, fcwT + (long long)l * 4 * HD * HD, HD,
            fc_b + l * 4 * HD, nullptr, fc16, 4 * HD, HD, 1);
        // proj + residual -> fp32 h
        hgemm<128, 0><<<dim3(HD / 128, SQ / BM), 256, SMH>>>(
            fc16, 4 * HD, projwT + (long long)l * 4 * HD * HD, 4 * HD,
            proj_b + l * HD, h, h, HD, 4 * HD, 0);
    }
    ln_kernel<float><<<SQ, 256>>>(h, lnf_g, lnf_b, (float*)d_out);
}